// round 1
// baseline (speedup 1.0000x reference)
#include <cuda_runtime.h>
#include <math.h>

#define B_ 16
#define H_ 32
#define W_ 32
#define D_ 512
#define L_ 1024           // H_*W_
#define C_ 768
#define M_ (B_*L_)        // 16384 rows

// ---- static scratch (no allocations allowed) ----
__device__ float g_x [M_*D_];      // residual stream
__device__ float g_h [M_*D_];      // LN out / gated y (GEMM A operand)
__device__ float g_xg[M_*2*D_];    // input-proj output (x_in | gate)
__device__ float g_u [M_*D_];      // conv+silu output (scan input)
__device__ float g_y [M_*D_];      // scan accumulation
__device__ float g_ap [L_*D_];     // a_pow table (per current block)
__device__ float g_iap[L_*D_];     // 1/a_pow table

// ---------------- LayerNorm: one warp per row of 512 ----------------
__global__ void __launch_bounds__(256) ln_kernel(
    const float* __restrict__ x, const float* __restrict__ w,
    const float* __restrict__ b, float* __restrict__ out)
{
    int row  = blockIdx.x * 8 + (threadIdx.x >> 5);
    int lane = threadIdx.x & 31;
    const float* xr = x + (size_t)row * D_;
    float4 v[4];
    float s = 0.f, sq = 0.f;
#pragma unroll
    for (int i = 0; i < 4; i++) {
        v[i] = *(const float4*)(xr + i*128 + lane*4);
        s  += v[i].x + v[i].y + v[i].z + v[i].w;
        sq += v[i].x*v[i].x + v[i].y*v[i].y + v[i].z*v[i].z + v[i].w*v[i].w;
    }
#pragma unroll
    for (int o = 16; o; o >>= 1) {
        s  += __shfl_xor_sync(0xffffffffu, s,  o);
        sq += __shfl_xor_sync(0xffffffffu, sq, o);
    }
    float mu  = s * (1.0f / D_);
    float var = sq * (1.0f / D_) - mu * mu;
    float rs  = rsqrtf(var + 1e-5f);
    float* orow = out + (size_t)row * D_;
#pragma unroll
    for (int i = 0; i < 4; i++) {
        int col = i*128 + lane*4;
        float4 wv = *(const float4*)(w + col);
        float4 bv = *(const float4*)(b + col);
        float4 o;
        o.x = (v[i].x - mu) * rs * wv.x + bv.x;
        o.y = (v[i].y - mu) * rs * wv.y + bv.y;
        o.z = (v[i].z - mu) * rs * wv.z + bv.z;
        o.w = (v[i].w - mu) * rs * wv.w + bv.w;
        *(float4*)(orow + col) = o;
    }
}

// ---------------- SGEMM: 128x128x8 tile, 8x8 per thread ----------------
// MODE 0: C = A@B + bias ; MODE 1: C = R + A@B + bias
template<int MODE>
__global__ void __launch_bounds__(256) sgemm_kernel(
    const float* __restrict__ A, const float* __restrict__ B,
    const float* __restrict__ bias, const float* __restrict__ R,
    float* __restrict__ C, int M, int N, int K)
{
    __shared__ float As[8][128];
    __shared__ float Bs[8][128];
    int t  = threadIdx.x;
    int tx = t & 15, ty = t >> 4;
    int bm = blockIdx.y << 7, bn = blockIdx.x << 7;
    int arow = t >> 1, acol = (t & 1) << 2;
    int brow = t >> 5, bcol = (t & 31) << 2;
    const float* Ap = A + (size_t)(bm + arow) * K + acol;
    const float* Bp = B + (size_t)brow * N + bn + bcol;
    float acc[8][8] = {};
    int nk = K >> 3;
    for (int kb = 0; kb < nk; kb++) {
        float4 av = *(const float4*)Ap;
        float4 bv = *(const float4*)Bp;
        Ap += 8;
        Bp += (size_t)8 * N;
        As[acol+0][arow] = av.x;
        As[acol+1][arow] = av.y;
        As[acol+2][arow] = av.z;
        As[acol+3][arow] = av.w;
        *(float4*)&Bs[brow][bcol] = bv;
        __syncthreads();
#pragma unroll
        for (int kk = 0; kk < 8; kk++) {
            float4 a0 = *(const float4*)&As[kk][ty << 2];
            float4 a1 = *(const float4*)&As[kk][64 + (ty << 2)];
            float4 b0 = *(const float4*)&Bs[kk][tx << 2];
            float4 b1 = *(const float4*)&Bs[kk][64 + (tx << 2)];
            float ra[8] = {a0.x,a0.y,a0.z,a0.w,a1.x,a1.y,a1.z,a1.w};
            float rb[8] = {b0.x,b0.y,b0.z,b0.w,b1.x,b1.y,b1.z,b1.w};
#pragma unroll
            for (int i = 0; i < 8; i++)
#pragma unroll
                for (int j = 0; j < 8; j++)
                    acc[i][j] += ra[i] * rb[j];
        }
        __syncthreads();
    }
#pragma unroll
    for (int i = 0; i < 8; i++) {
        int row = bm + ((i < 4) ? (ty << 2) + i : 64 + (ty << 2) + i - 4);
#pragma unroll
        for (int jh = 0; jh < 2; jh++) {
            int col = bn + jh*64 + (tx << 2);
            float4 bb4 = *(const float4*)(bias + col);
            float4 o;
            o.x = acc[i][jh*4+0] + bb4.x;
            o.y = acc[i][jh*4+1] + bb4.y;
            o.z = acc[i][jh*4+2] + bb4.z;
            o.w = acc[i][jh*4+3] + bb4.w;
            if (MODE == 1) {
                float4 r4 = *(const float4*)(R + (size_t)row * N + col);
                o.x += r4.x; o.y += r4.y; o.z += r4.z; o.w += r4.w;
            }
            *(float4*)(C + (size_t)row * N + col) = o;
        }
    }
}

// ---------------- depthwise 3x3 conv (SAME, zero pad) + bias + SiLU ----------------
__global__ void __launch_bounds__(512) conv_silu_kernel(
    const float* __restrict__ xg, const float* __restrict__ cw,
    const float* __restrict__ cb, float* __restrict__ u)
{
    int cell = blockIdx.x;                 // b*1024 + h*32 + w
    int d = threadIdx.x;
    int w = cell & 31, h = (cell >> 5) & 31, b = cell >> 10;
    float acc = 0.f;
#pragma unroll
    for (int kh = -1; kh <= 1; kh++) {
        int hh = h + kh;
        if ((unsigned)hh >= 32u) continue;
#pragma unroll
        for (int kw = -1; kw <= 1; kw++) {
            int ww = w + kw;
            if ((unsigned)ww >= 32u) continue;
            float xv = xg[(size_t)((b << 10) + (hh << 5) + ww) * (2*D_) + d];
            float wv = cw[((kh+1)*3 + (kw+1)) * D_ + d];
            acc += xv * wv;
        }
    }
    float z = acc + cb[d];
    u[(size_t)cell * D_ + d] = z / (1.f + expf(-z));   // silu
}

// ---------------- a_pow tables (must replicate clamped log-domain form) ----------------
__global__ void __launch_bounds__(512) ap_kernel(const float* __restrict__ alog)
{
    int d = threadIdx.x, t = blockIdx.x;
    float a = 1.f / (1.f + expf(-alog[d]));
    a = fminf(fmaxf(a, 1e-4f), 1.f - 1e-4f);
    float ap = fmaxf(expf((float)t * logf(a)), 1e-20f);
    g_ap [t*D_ + d] = ap;
    g_iap[t*D_ + d] = 1.f / ap;
}

// ---------------- row-major scan: fwd prefix + bwd suffix, writes s-terms into y ----------------
__global__ void __launch_bounds__(256) scan_row_kernel(
    const float* __restrict__ u, const float* __restrict__ bvec,
    float* __restrict__ y)
{
    int tid = blockIdx.x * 256 + threadIdx.x;   // 8192 = B*D
    int b = tid >> 9, d = tid & 511;
    const float* up = u + (size_t)b * L_ * D_ + d;
    float* yp = y + (size_t)b * L_ * D_ + d;
    float bd = bvec[d];
    float s = 0.f;
    for (int t = 0; t < L_; t++) {
        float v = up[(size_t)t * D_] * bd * g_iap[t*D_ + d];
        s += v;
        yp[(size_t)t * D_] = g_ap[t*D_ + d] * s;
    }
    s = 0.f;
    for (int t = L_ - 1; t >= 0; t--) {
        int rt = L_ - 1 - t;
        float v = up[(size_t)t * D_] * bd * g_iap[rt*D_ + d];
        s += v;
        yp[(size_t)t * D_] += g_ap[rt*D_ + d] * s;
    }
}

// ---------------- column-major scan (accumulates into y) ----------------
__global__ void __launch_bounds__(256) scan_col_kernel(
    const float* __restrict__ u, const float* __restrict__ bvec,
    float* __restrict__ y)
{
    int tid = blockIdx.x * 256 + threadIdx.x;
    int b = tid >> 9, d = tid & 511;
    const float* up = u + (size_t)b * L_ * D_ + d;
    float* yp = y + (size_t)b * L_ * D_ + d;
    float bd = bvec[d];
    float s = 0.f;
    for (int l = 0; l < L_; l++) {
        int pos = ((l & 31) << 5) + (l >> 5);    // (h=l%32, w=l/32) -> h*32+w
        float v = up[(size_t)pos * D_] * bd * g_iap[l*D_ + d];
        s += v;
        yp[(size_t)pos * D_] += g_ap[l*D_ + d] * s;
    }
    s = 0.f;
    for (int l = L_ - 1; l >= 0; l--) {
        int rl = L_ - 1 - l;
        int pos = ((l & 31) << 5) + (l >> 5);
        float v = up[(size_t)pos * D_] * bd * g_iap[rl*D_ + d];
        s += v;
        yp[(size_t)pos * D_] += g_ap[rl*D_ + d] * s;
    }
}

// ---------------- combine: y = 0.25*c*sum_scans + d*u ; multiply by sigmoid(gate) ----------------
__global__ void __launch_bounds__(256) combine_kernel(
    const float* __restrict__ y, const float* __restrict__ u,
    const float* __restrict__ xg, const float* __restrict__ cvec,
    const float* __restrict__ dvec, float* __restrict__ g)
{
    int i = blockIdx.x * 256 + threadIdx.x;
    int d = i & 511;
    size_t row = (size_t)(i >> 9);
    float yv = 0.25f * cvec[d] * y[i] + dvec[d] * u[i];
    float gt = xg[row * (2*D_) + D_ + d];
    g[i] = yv * (1.f / (1.f + expf(-gt)));
}

// ---------------- mean pool over the 1024 grid positions (double accumulator) ----------------
__global__ void __launch_bounds__(512) pool_kernel(
    const float* __restrict__ h, float* __restrict__ out)
{
    int b = blockIdx.x, d = threadIdx.x;
    const float* p = h + (size_t)b * L_ * D_ + d;
    double acc = 0.0;
    for (int t = 0; t < L_; t++) acc += (double)p[(size_t)t * D_];
    out[b*D_ + d] = (float)(acc * (1.0 / 1024.0));
}

extern "C" void kernel_launch(void* const* d_in, const int* in_sizes, int n_in,
                              void* d_out, int out_size)
{
    const float* tokens = (const float*)d_in[0];
    const float* ipw = (const float*)d_in[1];
    const float* ipb = (const float*)d_in[2];
    const float* nw  = (const float*)d_in[3];
    const float* nb  = (const float*)d_in[4];
    const float* iw  = (const float*)d_in[5];
    const float* ib  = (const float*)d_in[6];
    const float* cw  = (const float*)d_in[7];
    const float* cb  = (const float*)d_in[8];
    const float* al  = (const float*)d_in[9];
    const float* bb  = (const float*)d_in[10];
    const float* cc  = (const float*)d_in[11];
    const float* dd  = (const float*)d_in[12];
    const float* ow  = (const float*)d_in[13];
    const float* ob  = (const float*)d_in[14];
    const float* onw = (const float*)d_in[15];
    const float* onb = (const float*)d_in[16];
    float* out = (float*)d_out;

    float *px, *ph, *pxg, *pu, *py;
    cudaGetSymbolAddress((void**)&px,  g_x);
    cudaGetSymbolAddress((void**)&ph,  g_h);
    cudaGetSymbolAddress((void**)&pxg, g_xg);
    cudaGetSymbolAddress((void**)&pu,  g_u);
    cudaGetSymbolAddress((void**)&py,  g_y);

    // in_proj: (16384x768)@(768x512)
    sgemm_kernel<0><<<dim3(D_/128, M_/128), 256>>>(tokens, ipw, ipb, nullptr, px, M_, D_, C_);

    for (int i = 0; i < 4; i++) {
        ln_kernel<<<M_/8, 256>>>(px, nw + i*D_, nb + i*D_, ph);
        sgemm_kernel<0><<<dim3(2*D_/128, M_/128), 256>>>(
            ph, iw + (size_t)i*D_*2*D_, ib + i*2*D_, nullptr, pxg, M_, 2*D_, D_);
        conv_silu_kernel<<<M_, 512>>>(pxg, cw + (size_t)i*9*D_, cb + i*D_, pu);
        ap_kernel<<<L_, 512>>>(al + i*D_);
        scan_row_kernel<<<32, 256>>>(pu, bb + i*D_, py);
        scan_col_kernel<<<32, 256>>>(pu, bb + i*D_, py);
        combine_kernel<<<(M_*D_)/256, 256>>>(py, pu, pxg, cc + i*D_, dd + i*D_, ph);
        sgemm_kernel<1><<<dim3(D_/128, M_/128), 256>>>(
            ph, ow + (size_t)i*D_*D_, ob + i*D_, px, px, M_, D_, D_);
    }

    ln_kernel<<<M_/8, 256>>>(px, onw, onb, ph);
    pool_kernel<<<B_, 512>>>(ph, out);
}

// round 2
// speedup vs baseline: 2.9927x; 2.9927x over previous
#include <cuda_runtime.h>
#include <math.h>

#define B_ 16
#define H_ 32
#define W_ 32
#define D_ 512
#define L_ 1024           // H_*W_
#define C_ 768
#define M_ (B_*L_)        // 16384 rows
#define NCH 16
#define CHL 64

// ---- static scratch (no allocations allowed) ----
__device__ float g_x [M_*D_];           // residual stream
__device__ float g_h [M_*D_];           // LN out / gated y (GEMM A operand)
__device__ float g_xg[M_*2*D_];         // input-proj output (x_in | gate)
__device__ float g_u [M_*D_];           // conv+silu output (scan input)
__device__ float g_ap [L_*D_];          // a_pow table (per current block)
__device__ float g_iap[L_*D_];          // 1/a_pow table
__device__ float g_cs [4*B_*NCH*D_];    // chunk partial sums
__device__ float g_y4[(size_t)4*M_*D_]; // 4 direction scan outputs

__device__ __forceinline__ unsigned f2tf(float x){
    unsigned r; asm("cvt.rna.tf32.f32 %0, %1;" : "=r"(r) : "f"(x)); return r;
}

// ---------------- LayerNorm: one warp per row of 512 ----------------
__global__ void __launch_bounds__(256) ln_kernel(
    const float* __restrict__ x, const float* __restrict__ w,
    const float* __restrict__ b, float* __restrict__ out)
{
    int row  = blockIdx.x * 8 + (threadIdx.x >> 5);
    int lane = threadIdx.x & 31;
    const float* xr = x + (size_t)row * D_;
    float4 v[4];
    float s = 0.f, sq = 0.f;
#pragma unroll
    for (int i = 0; i < 4; i++) {
        v[i] = *(const float4*)(xr + i*128 + lane*4);
        s  += v[i].x + v[i].y + v[i].z + v[i].w;
        sq += v[i].x*v[i].x + v[i].y*v[i].y + v[i].z*v[i].z + v[i].w*v[i].w;
    }
#pragma unroll
    for (int o = 16; o; o >>= 1) {
        s  += __shfl_xor_sync(0xffffffffu, s,  o);
        sq += __shfl_xor_sync(0xffffffffu, sq, o);
    }
    float mu  = s * (1.0f / D_);
    float var = sq * (1.0f / D_) - mu * mu;
    float rs  = rsqrtf(var + 1e-5f);
    float* orow = out + (size_t)row * D_;
#pragma unroll
    for (int i = 0; i < 4; i++) {
        int col = i*128 + lane*4;
        float4 wv = *(const float4*)(w + col);
        float4 bv = *(const float4*)(b + col);
        float4 o;
        o.x = (v[i].x - mu) * rs * wv.x + bv.x;
        o.y = (v[i].y - mu) * rs * wv.y + bv.y;
        o.z = (v[i].z - mu) * rs * wv.z + bv.z;
        o.w = (v[i].w - mu) * rs * wv.w + bv.w;
        *(float4*)(orow + col) = o;
    }
}

// ---------------- tf32 tensor-core GEMM: 128x128x32 tile, mma.m16n8k8 ----------------
// MODE 0: C = A@B + bias ; MODE 1: C = R + A@B + bias
template<int MODE>
__global__ void __launch_bounds__(256, 2) gemm_tc(
    const float* __restrict__ A, const float* __restrict__ Bm,
    const float* __restrict__ bias, const float* __restrict__ R,
    float* __restrict__ C, int M, int N, int K)
{
    __shared__ unsigned As[128][36];   // [m][k] : bank (4m+k)%32 conflict-free
    __shared__ unsigned Bs[32][136];   // [k][n] : bank (8k+n)%32 conflict-free
    int t = threadIdx.x;
    int lane = t & 31, wid = t >> 5;
    int bm = blockIdx.y << 7, bn = blockIdx.x << 7;
    int warpM = wid >> 2, warpN = wid & 3;     // 2 x 4 warp grid, 64x32 per warp
    int tg = lane & 3, gid = lane >> 2;

    float acc[4][4][4];
#pragma unroll
    for (int i = 0; i < 4; i++)
#pragma unroll
        for (int j = 0; j < 4; j++)
#pragma unroll
            for (int k = 0; k < 4; k++) acc[i][j][k] = 0.f;

    int arow = t >> 3, acol = (t & 7) << 2;    // A: 32 rows/iter, 4 iters
    int brow = t >> 5, bcol = (t & 31) << 2;   // B: 8 rows/iter, 4 iters

    int nkb = K >> 5;
    for (int kb = 0; kb < nkb; kb++) {
#pragma unroll
        for (int i = 0; i < 4; i++) {
            int r = arow + i * 32;
            float4 v = *(const float4*)(A + (size_t)(bm + r) * K + kb*32 + acol);
            As[r][acol+0] = f2tf(v.x);
            As[r][acol+1] = f2tf(v.y);
            As[r][acol+2] = f2tf(v.z);
            As[r][acol+3] = f2tf(v.w);
        }
#pragma unroll
        for (int i = 0; i < 4; i++) {
            int r = brow + i * 8;
            float4 v = *(const float4*)(Bm + (size_t)(kb*32 + r) * N + bn + bcol);
            Bs[r][bcol+0] = f2tf(v.x);
            Bs[r][bcol+1] = f2tf(v.y);
            Bs[r][bcol+2] = f2tf(v.z);
            Bs[r][bcol+3] = f2tf(v.w);
        }
        __syncthreads();
#pragma unroll
        for (int ks = 0; ks < 4; ks++) {
            int k0 = ks << 3;
            unsigned af[4][4], bf[4][2];
#pragma unroll
            for (int mt = 0; mt < 4; mt++) {
                int m0 = warpM*64 + mt*16;
                af[mt][0] = As[m0 + gid    ][k0 + tg];
                af[mt][1] = As[m0 + gid + 8][k0 + tg];
                af[mt][2] = As[m0 + gid    ][k0 + tg + 4];
                af[mt][3] = As[m0 + gid + 8][k0 + tg + 4];
            }
#pragma unroll
            for (int nt = 0; nt < 4; nt++) {
                int n0 = warpN*32 + nt*8;
                bf[nt][0] = Bs[k0 + tg    ][n0 + gid];
                bf[nt][1] = Bs[k0 + tg + 4][n0 + gid];
            }
#pragma unroll
            for (int mt = 0; mt < 4; mt++)
#pragma unroll
                for (int nt = 0; nt < 4; nt++) {
                    asm volatile(
                        "mma.sync.aligned.m16n8k8.row.col.f32.tf32.tf32.f32 "
                        "{%0,%1,%2,%3}, {%4,%5,%6,%7}, {%8,%9}, {%0,%1,%2,%3};"
                        : "+f"(acc[mt][nt][0]), "+f"(acc[mt][nt][1]),
                          "+f"(acc[mt][nt][2]), "+f"(acc[mt][nt][3])
                        : "r"(af[mt][0]), "r"(af[mt][1]), "r"(af[mt][2]), "r"(af[mt][3]),
                          "r"(bf[nt][0]), "r"(bf[nt][1]));
                }
        }
        __syncthreads();
    }

    // epilogue
#pragma unroll
    for (int mt = 0; mt < 4; mt++) {
        int r0 = bm + warpM*64 + mt*16 + gid;
#pragma unroll
        for (int nt = 0; nt < 4; nt++) {
            int col = bn + warpN*32 + nt*8 + 2*tg;
            float b0 = bias[col], b1 = bias[col+1];
            float o0 = acc[mt][nt][0] + b0;
            float o1 = acc[mt][nt][1] + b1;
            float o2 = acc[mt][nt][2] + b0;
            float o3 = acc[mt][nt][3] + b1;
            if (MODE == 1) {
                float2 ra = *(const float2*)(R + (size_t)r0 * N + col);
                float2 rb = *(const float2*)(R + (size_t)(r0+8) * N + col);
                o0 += ra.x; o1 += ra.y; o2 += rb.x; o3 += rb.y;
            }
            *(float2*)(C + (size_t)r0 * N + col)     = make_float2(o0, o1);
            *(float2*)(C + (size_t)(r0+8) * N + col) = make_float2(o2, o3);
        }
    }
}

// ---------------- depthwise 3x3 conv (SAME, zero pad) + bias + SiLU ----------------
__global__ void __launch_bounds__(512) conv_silu_kernel(
    const float* __restrict__ xg, const float* __restrict__ cw,
    const float* __restrict__ cb, float* __restrict__ u)
{
    int cell = blockIdx.x;                 // b*1024 + h*32 + w
    int d = threadIdx.x;
    int w = cell & 31, h = (cell >> 5) & 31, b = cell >> 10;
    float acc = 0.f;
#pragma unroll
    for (int kh = -1; kh <= 1; kh++) {
        int hh = h + kh;
        if ((unsigned)hh >= 32u) continue;
#pragma unroll
        for (int kw = -1; kw <= 1; kw++) {
            int ww = w + kw;
            if ((unsigned)ww >= 32u) continue;
            float xv = xg[(size_t)((b << 10) + (hh << 5) + ww) * (2*D_) + d];
            float wv = cw[((kh+1)*3 + (kw+1)) * D_ + d];
            acc += xv * wv;
        }
    }
    float z = acc + cb[d];
    u[(size_t)cell * D_ + d] = z / (1.f + expf(-z));   // silu
}

// ---------------- a_pow tables (replicates clamped log-domain form) ----------------
__global__ void __launch_bounds__(512) ap_kernel(const float* __restrict__ alog)
{
    int d = threadIdx.x, t = blockIdx.x;
    float a = 1.f / (1.f + expf(-alog[d]));
    a = fminf(fmaxf(a, 1e-4f), 1.f - 1e-4f);
    float ap = fmaxf(expf((float)t * logf(a)), 1e-20f);
    g_ap [t*D_ + d] = ap;
    g_iap[t*D_ + d] = 1.f / ap;
}

// scan position mapping: dir 0=rowF,1=rowB,2=colF,3=colB ; t = index within scan order
__device__ __forceinline__ int dir_pos(int dir, int t) {
    int l = (dir & 1) ? (L_ - 1 - t) : t;
    if (dir >= 2) l = ((l & 31) << 5) + (l >> 5);   // (h=l%32,w=l/32) -> h*32+w
    return l;
}

// ---------------- pass A: per-chunk partial sums ----------------
__global__ void __launch_bounds__(256) scanA(
    const float* __restrict__ u, const float* __restrict__ bvec)
{
    int tid = blockIdx.x * 256 + threadIdx.x;   // 4*16*16*512 = 524288
    int d   = tid & 511;
    int c   = (tid >> 9) & 15;
    int b   = (tid >> 13) & 15;
    int dir = tid >> 17;
    float bd = bvec[d];
    const float* ub = u + ((size_t)b << 10) * D_ + d;
    float s = 0.f;
#pragma unroll 4
    for (int i = 0; i < CHL; i++) {
        int t = c * CHL + i;
        int pos = dir_pos(dir, t);
        s += ub[(size_t)pos * D_] * bd * g_iap[t*D_ + d];
    }
    g_cs[tid] = s;
}

// ---------------- pass B: exclusive prefix over 16 chunk sums ----------------
__global__ void __launch_bounds__(256) scanB()
{
    int tid = blockIdx.x * 256 + threadIdx.x;   // 4*16*512 = 32768
    int d = tid & 511;
    int b = (tid >> 9) & 15;
    int dir = tid >> 13;
    size_t base = (((size_t)dir * B_ + b) * NCH) * D_ + d;
    float s = 0.f;
#pragma unroll
    for (int c = 0; c < NCH; c++) {
        float v = g_cs[base + (size_t)c * D_];
        g_cs[base + (size_t)c * D_] = s;
        s += v;
    }
}

// ---------------- pass C: replay chunk with offset, write ap*s ----------------
__global__ void __launch_bounds__(256) scanC(
    const float* __restrict__ u, const float* __restrict__ bvec)
{
    int tid = blockIdx.x * 256 + threadIdx.x;
    int d   = tid & 511;
    int c   = (tid >> 9) & 15;
    int b   = (tid >> 13) & 15;
    int dir = tid >> 17;
    float bd = bvec[d];
    const float* ub = u + ((size_t)b << 10) * D_ + d;
    float* yb = g_y4 + (size_t)dir * M_ * D_ + ((size_t)b << 10) * D_ + d;
    float s = g_cs[tid];
#pragma unroll 4
    for (int i = 0; i < CHL; i++) {
        int t = c * CHL + i;
        int pos = dir_pos(dir, t);
        s += ub[(size_t)pos * D_] * bd * g_iap[t*D_ + d];
        yb[(size_t)pos * D_] = g_ap[t*D_ + d] * s;
    }
}

// ---------------- combine: y = 0.25*c*sum4 + d*u ; multiply by sigmoid(gate) ----------------
__global__ void __launch_bounds__(256) combine_kernel(
    const float* __restrict__ u, const float* __restrict__ xg,
    const float* __restrict__ cvec, const float* __restrict__ dvec,
    float* __restrict__ g)
{
    int i = blockIdx.x * 256 + threadIdx.x;
    int d = i & 511;
    size_t row = (size_t)(i >> 9);
    const size_t MD = (size_t)M_ * D_;
    float ysum = g_y4[i] + g_y4[i + MD] + g_y4[i + 2*MD] + g_y4[i + 3*MD];
    float yv = 0.25f * cvec[d] * ysum + dvec[d] * u[i];
    float gt = xg[row * (2*D_) + D_ + d];
    g[i] = yv * (1.f / (1.f + expf(-gt)));
}

// ---------------- mean pool over the 1024 grid positions ----------------
__global__ void __launch_bounds__(512) pool_kernel(
    const float* __restrict__ h, float* __restrict__ out)
{
    int b = blockIdx.x, d = threadIdx.x;
    const float* p = h + (size_t)b * L_ * D_ + d;
    double acc = 0.0;
    for (int t = 0; t < L_; t++) acc += (double)p[(size_t)t * D_];
    out[b*D_ + d] = (float)(acc * (1.0 / 1024.0));
}

extern "C" void kernel_launch(void* const* d_in, const int* in_sizes, int n_in,
                              void* d_out, int out_size)
{
    const float* tokens = (const float*)d_in[0];
    const float* ipw = (const float*)d_in[1];
    const float* ipb = (const float*)d_in[2];
    const float* nw  = (const float*)d_in[3];
    const float* nb  = (const float*)d_in[4];
    const float* iw  = (const float*)d_in[5];
    const float* ib  = (const float*)d_in[6];
    const float* cw  = (const float*)d_in[7];
    const float* cb  = (const float*)d_in[8];
    const float* al  = (const float*)d_in[9];
    const float* bb  = (const float*)d_in[10];
    const float* cc  = (const float*)d_in[11];
    const float* dd  = (const float*)d_in[12];
    const float* ow  = (const float*)d_in[13];
    const float* ob  = (const float*)d_in[14];
    const float* onw = (const float*)d_in[15];
    const float* onb = (const float*)d_in[16];
    float* out = (float*)d_out;

    float *px, *ph, *pxg, *pu;
    cudaGetSymbolAddress((void**)&px,  g_x);
    cudaGetSymbolAddress((void**)&ph,  g_h);
    cudaGetSymbolAddress((void**)&pxg, g_xg);
    cudaGetSymbolAddress((void**)&pu,  g_u);

    // in_proj: (16384x768)@(768x512)
    gemm_tc<0><<<dim3(D_/128, M_/128), 256>>>(tokens, ipw, ipb, nullptr, px, M_, D_, C_);

    for (int i = 0; i < 4; i++) {
        ln_kernel<<<M_/8, 256>>>(px, nw + i*D_, nb + i*D_, ph);
        gemm_tc<0><<<dim3(2*D_/128, M_/128), 256>>>(
            ph, iw + (size_t)i*D_*2*D_, ib + i*2*D_, nullptr, pxg, M_, 2*D_, D_);
        conv_silu_kernel<<<M_, 512>>>(pxg, cw + (size_t)i*9*D_, cb + i*D_, pu);
        ap_kernel<<<L_, 512>>>(al + i*D_);
        scanA<<<(4*B_*NCH*D_)/256, 256>>>(pu, bb + i*D_);
        scanB<<<(4*B_*D_)/256, 256>>>();
        scanC<<<(4*B_*NCH*D_)/256, 256>>>(pu, bb + i*D_);
        combine_kernel<<<(M_*D_)/256, 256>>>(pu, pxg, cc + i*D_, dd + i*D_, ph);
        gemm_tc<1><<<dim3(D_/128, M_/128), 256>>>(
            ph, ow + (size_t)i*D_*D_, ob + i*D_, px, px, M_, D_, D_);
    }

    ln_kernel<<<M_/8, 256>>>(px, onw, onb, ph);
    pool_kernel<<<B_, 512>>>(ph, out);
}

// round 6
// speedup vs baseline: 3.2171x; 1.0750x over previous
#include <cuda_runtime.h>
#include <math.h>

#define B_ 16
#define H_ 32
#define W_ 32
#define D_ 512
#define L_ 1024           // H_*W_
#define C_ 768
#define M_ (B_*L_)        // 16384 rows
#define NCH 32
#define CHL 32

// ---- static scratch (no allocations allowed) ----
__device__ float g_x [M_*D_];           // residual stream
__device__ float g_h [M_*D_];           // LN out / gated y (GEMM A operand)
__device__ float g_xg[M_*2*D_];         // input-proj output (x_in | gate)
__device__ float g_u [M_*D_];           // conv+silu output (scan input)
__device__ float g_yrow[M_*D_];         // row-orientation scan sum
__device__ float g_ap [L_*D_];          // a_pow table (per current block)
__device__ float g_iap[L_*D_];          // 1/a_pow table
__device__ float g_cs [4*B_*NCH*D_];    // chunk partial sums [dir][b][chunk][d]

__device__ __forceinline__ unsigned f2tf(float x){
    unsigned r; asm("cvt.rna.tf32.f32 %0, %1;" : "=r"(r) : "f"(x)); return r;
}
__device__ __forceinline__ void cpasync16(unsigned saddr, const float* g){
    asm volatile("cp.async.cg.shared.global [%0], [%1], 16;" :: "r"(saddr), "l"(g));
}

// ---------------- LayerNorm: one warp per row of 512 ----------------
__global__ void __launch_bounds__(256) ln_kernel(
    const float* __restrict__ x, const float* __restrict__ w,
    const float* __restrict__ b, float* __restrict__ out)
{
    int row  = blockIdx.x * 8 + (threadIdx.x >> 5);
    int lane = threadIdx.x & 31;
    const float* xr = x + (size_t)row * D_;
    float4 v[4];
    float s = 0.f, sq = 0.f;
#pragma unroll
    for (int i = 0; i < 4; i++) {
        v[i] = *(const float4*)(xr + i*128 + lane*4);
        s  += v[i].x + v[i].y + v[i].z + v[i].w;
        sq += v[i].x*v[i].x + v[i].y*v[i].y + v[i].z*v[i].z + v[i].w*v[i].w;
    }
#pragma unroll
    for (int o = 16; o; o >>= 1) {
        s  += __shfl_xor_sync(0xffffffffu, s,  o);
        sq += __shfl_xor_sync(0xffffffffu, sq, o);
    }
    float mu  = s * (1.0f / D_);
    float var = sq * (1.0f / D_) - mu * mu;
    float rs  = rsqrtf(var + 1e-5f);
    float* orow = out + (size_t)row * D_;
#pragma unroll
    for (int i = 0; i < 4; i++) {
        int col = i*128 + lane*4;
        float4 wv = *(const float4*)(w + col);
        float4 bv = *(const float4*)(b + col);
        float4 o;
        o.x = (v[i].x - mu) * rs * wv.x + bv.x;
        o.y = (v[i].y - mu) * rs * wv.y + bv.y;
        o.z = (v[i].z - mu) * rs * wv.z + bv.z;
        o.w = (v[i].w - mu) * rs * wv.w + bv.w;
        *(float4*)(orow + col) = o;
    }
}

// ---------------- tf32 GEMM: 128x128x32 tile, cp.async double-buffered ----------------
// MODE 0: C = A@B + bias ; MODE 1: C = R + A@B + bias
// smem: As[2][128][36] fp32 raw, Bs[2][32][136] fp32 raw (convert to tf32 in regs)
template<int MODE>
__global__ void __launch_bounds__(256, 2) gemm_tc(
    const float* __restrict__ A, const float* __restrict__ Bm,
    const float* __restrict__ bias, const float* __restrict__ R,
    float* __restrict__ C, int M, int N, int K)
{
    extern __shared__ float sm_[];
    float* As = sm_;                 // 2*128*36 = 9216 floats
    float* Bs = sm_ + 9216;          // 2*32*136 = 8704 floats
    unsigned sAs = (unsigned)__cvta_generic_to_shared(As);
    unsigned sBs = (unsigned)__cvta_generic_to_shared(Bs);

    int t = threadIdx.x;
    int lane = t & 31, wid = t >> 5;
    int bm = blockIdx.y << 7, bn = blockIdx.x << 7;
    int warpM = wid >> 2, warpN = wid & 3;     // 2 x 4 warp grid, 64x32 per warp
    int tg = lane & 3, gid = lane >> 2;

    float acc[4][4][4];
#pragma unroll
    for (int i = 0; i < 4; i++)
#pragma unroll
        for (int j = 0; j < 4; j++)
#pragma unroll
            for (int k = 0; k < 4; k++) acc[i][j][k] = 0.f;

    auto issue = [&](int kb, int buf) {
#pragma unroll
        for (int j = 0; j < 4; j++) {
            int idx = t + 256*j;
            int r = idx >> 3, c4 = (idx & 7) << 2;
            cpasync16(sAs + (unsigned)(buf*4608 + r*36 + c4)*4,
                      A + (size_t)(bm + r) * K + kb*32 + c4);
        }
#pragma unroll
        for (int j = 0; j < 4; j++) {
            int idx = t + 256*j;
            int r = idx >> 5, c4 = (idx & 31) << 2;
            cpasync16(sBs + (unsigned)(buf*4352 + r*136 + c4)*4,
                      Bm + (size_t)(kb*32 + r) * N + bn + c4);
        }
        asm volatile("cp.async.commit_group;");
    };

    int nkb = K >> 5;
    issue(0, 0);
    for (int kb = 0; kb < nkb; kb++) {
        int buf = kb & 1;
        if (kb + 1 < nkb) {
            issue(kb + 1, buf ^ 1);
            asm volatile("cp.async.wait_group 1;");
        } else {
            asm volatile("cp.async.wait_group 0;");
        }
        __syncthreads();
        const float* A0 = As + buf*4608;
        const float* B0 = Bs + buf*4352;
#pragma unroll
        for (int ks = 0; ks < 4; ks++) {
            int k0 = ks << 3;
            unsigned af[4][4], bf[4][2];
#pragma unroll
            for (int mt = 0; mt < 4; mt++) {
                int m0 = warpM*64 + mt*16;
                af[mt][0] = f2tf(A0[(m0 + gid    )*36 + k0 + tg]);
                af[mt][1] = f2tf(A0[(m0 + gid + 8)*36 + k0 + tg]);
                af[mt][2] = f2tf(A0[(m0 + gid    )*36 + k0 + tg + 4]);
                af[mt][3] = f2tf(A0[(m0 + gid + 8)*36 + k0 + tg + 4]);
            }
#pragma unroll
            for (int nt = 0; nt < 4; nt++) {
                int n0 = warpN*32 + nt*8;
                bf[nt][0] = f2tf(B0[(k0 + tg    )*136 + n0 + gid]);
                bf[nt][1] = f2tf(B0[(k0 + tg + 4)*136 + n0 + gid]);
            }
#pragma unroll
            for (int mt = 0; mt < 4; mt++)
#pragma unroll
                for (int nt = 0; nt < 4; nt++) {
                    asm volatile(
                        "mma.sync.aligned.m16n8k8.row.col.f32.tf32.tf32.f32 "
                        "{%0,%1,%2,%3}, {%4,%5,%6,%7}, {%8,%9}, {%0,%1,%2,%3};"
                        : "+f"(acc[mt][nt][0]), "+f"(acc[mt][nt][1]),
                          "+f"(acc[mt][nt][2]), "+f"(acc[mt][nt][3])
                        : "r"(af[mt][0]), "r"(af[mt][1]), "r"(af[mt][2]), "r"(af[mt][3]),
                          "r"(bf[nt][0]), "r"(bf[nt][1]));
                }
        }
        __syncthreads();
    }

    // epilogue
#pragma unroll
    for (int mt = 0; mt < 4; mt++) {
        int r0 = bm + warpM*64 + mt*16 + gid;
#pragma unroll
        for (int nt = 0; nt < 4; nt++) {
            int col = bn + warpN*32 + nt*8 + 2*tg;
            float b0 = bias[col], b1 = bias[col+1];
            float o0 = acc[mt][nt][0] + b0;
            float o1 = acc[mt][nt][1] + b1;
            float o2 = acc[mt][nt][2] + b0;
            float o3 = acc[mt][nt][3] + b1;
            if (MODE == 1) {
                float2 ra = *(const float2*)(R + (size_t)r0 * N + col);
                float2 rb = *(const float2*)(R + (size_t)(r0+8) * N + col);
                o0 += ra.x; o1 += ra.y; o2 += rb.x; o3 += rb.y;
            }
            *(float2*)(C + (size_t)r0 * N + col)     = make_float2(o0, o1);
            *(float2*)(C + (size_t)(r0+8) * N + col) = make_float2(o2, o3);
        }
    }
}

// ---------------- depthwise 3x3 conv + bias + SiLU, register-shifted window ----------------
__global__ void __launch_bounds__(512) conv_silu_kernel(
    const float* __restrict__ xg, const float* __restrict__ cw,
    const float* __restrict__ cb, float* __restrict__ u)
{
    int bh = blockIdx.x;              // b*32 + h
    int d = threadIdx.x;
    int h = bh & 31, b = bh >> 5;
    float Wk[3][3];
#pragma unroll
    for (int r = 0; r < 3; r++)
#pragma unroll
        for (int c = 0; c < 3; c++) Wk[r][c] = cw[(r*3 + c)*D_ + d];
    float bias = cb[d];
    const float* base = xg + ((size_t)(b << 10)) * (2*D_) + d;
    bool hm = h > 0, hp = h < 31;
    float xm0 = 0.f, xm1 = 0.f, xm2 = 0.f;
    float xc0 = hm ? base[(size_t)((h-1)*32)*(2*D_)] : 0.f;
    float xc1 =      base[(size_t)( h   *32)*(2*D_)];
    float xc2 = hp ? base[(size_t)((h+1)*32)*(2*D_)] : 0.f;
    float* uo = u + (size_t)((b << 10) + (h << 5)) * D_ + d;
#pragma unroll 4
    for (int w = 0; w < 32; w++) {
        float xp0 = 0.f, xp1 = 0.f, xp2 = 0.f;
        if (w < 31) {
            xp0 = hm ? base[(size_t)((h-1)*32 + w+1)*(2*D_)] : 0.f;
            xp1 =      base[(size_t)( h   *32 + w+1)*(2*D_)];
            xp2 = hp ? base[(size_t)((h+1)*32 + w+1)*(2*D_)] : 0.f;
        }
        float acc = bias;
        acc += xm0*Wk[0][0] + xc0*Wk[0][1] + xp0*Wk[0][2];
        acc += xm1*Wk[1][0] + xc1*Wk[1][1] + xp1*Wk[1][2];
        acc += xm2*Wk[2][0] + xc2*Wk[2][1] + xp2*Wk[2][2];
        uo[(size_t)w * D_] = acc / (1.f + expf(-acc));
        xm0 = xc0; xm1 = xc1; xm2 = xc2;
        xc0 = xp0; xc1 = xp1; xc2 = xp2;
    }
}

// ---------------- a_pow tables (replicates clamped log-domain form) ----------------
__global__ void __launch_bounds__(512) ap_kernel(const float* __restrict__ alog)
{
    int d = threadIdx.x, t = blockIdx.x;
    float a = 1.f / (1.f + expf(-alog[d]));
    a = fminf(fmaxf(a, 1e-4f), 1.f - 1e-4f);
    float ap = fmaxf(expf((float)t * logf(a)), 1e-20f);
    g_ap [t*D_ + d] = ap;
    g_iap[t*D_ + d] = 1.f / ap;
}

// ---------------- pass A: per-chunk fwd+bwd partial sums, both orientations ----------------
__global__ void __launch_bounds__(256) scanA(
    const float* __restrict__ u, const float* __restrict__ bvec)
{
    int tid = blockIdx.x * 256 + threadIdx.x;   // 2*16*32*512 = 524288
    int d      = tid & 511;
    int c      = (tid >> 9) & 31;
    int b      = (tid >> 14) & 15;
    int orient = tid >> 18;                      // 0=row, 1=col
    float bd = bvec[d];
    const float* ub = u + ((size_t)b << 10) * D_ + d;
    float sf = 0.f, sb = 0.f;
#pragma unroll
    for (int i = 0; i < CHL; i++) {
        int s = c*CHL + i;                       // seq index (fwd)
        int pos = orient ? ((s & 31) << 5) + (s >> 5) : s;
        float uv = ub[(size_t)pos * D_] * bd;
        sf += uv * g_iap[s*D_ + d];
        sb += uv * g_iap[(L_-1-s)*D_ + d];
    }
    size_t dstr = (size_t)B_*NCH*D_;
    size_t base = (size_t)(orient*2) * dstr + ((size_t)b*NCH)*D_ + d;
    g_cs[base + (size_t)c*D_] = sf;
    g_cs[base + dstr + (size_t)(NCH-1-c)*D_] = sb;
}

// ---------------- pass B: exclusive prefix over 32 chunk sums per direction ----------------
__global__ void __launch_bounds__(256) scanB()
{
    int tid = blockIdx.x * 256 + threadIdx.x;   // 4*16*512 = 32768
    int d = tid & 511;
    int b = (tid >> 9) & 15;
    int dir = tid >> 13;
    size_t base = (((size_t)dir * B_ + b) * NCH) * D_ + d;
    float s = 0.f;
#pragma unroll
    for (int c = 0; c < NCH; c++) {
        float v = g_cs[base + (size_t)c * D_];
        g_cs[base + (size_t)c * D_] = s;
        s += v;
    }
}

// ---------------- pass C row: fwd+bwd replay, single store of summed terms ----------------
__global__ void __launch_bounds__(256) scanC_row(
    const float* __restrict__ u, const float* __restrict__ bvec)
{
    int tid = blockIdx.x * 256 + threadIdx.x;   // 16*32*512 = 262144
    int d = tid & 511;
    int c = (tid >> 9) & 31;
    int b = tid >> 14;
    float bd = bvec[d];
    size_t dstr = (size_t)B_*NCH*D_;
    size_t csb = ((size_t)b*NCH)*D_ + d;
    float off_f = g_cs[csb + (size_t)c*D_];
    float off_b = g_cs[dstr + csb + (size_t)(NCH-1-c)*D_];
    const float* ub = u + ((size_t)b << 10) * D_ + d;
    float* yr = g_yrow + ((size_t)b << 10) * D_ + d;
    float termb[CHL];
    float sb = off_b;
#pragma unroll
    for (int i = CHL-1; i >= 0; i--) {
        int s = c*CHL + i;
        int tb = L_-1-s;
        sb += ub[(size_t)s * D_] * bd * g_iap[tb*D_ + d];
        termb[i] = g_ap[tb*D_ + d] * sb;
    }
    float sf = off_f;
#pragma unroll
    for (int i = 0; i < CHL; i++) {
        int s = c*CHL + i;
        sf += ub[(size_t)s * D_] * bd * g_iap[s*D_ + d];
        yr[(size_t)s * D_] = g_ap[s*D_ + d] * sf + termb[i];
    }
}

// ---------------- pass C col + combine + gate: writes GEMM input h ----------------
__global__ void __launch_bounds__(256) scanC_col(
    const float* __restrict__ u, const float* __restrict__ xg,
    const float* __restrict__ bvec, const float* __restrict__ cvec,
    const float* __restrict__ dvec, float* __restrict__ hout)
{
    int tid = blockIdx.x * 256 + threadIdx.x;   // 262144
    int d = tid & 511;
    int c = (tid >> 9) & 31;
    int b = tid >> 14;
    float bd = bvec[d];
    size_t dstr = (size_t)B_*NCH*D_;
    size_t csb = ((size_t)b*NCH)*D_ + d;
    float off_f = g_cs[2*dstr + csb + (size_t)c*D_];
    float off_b = g_cs[3*dstr + csb + (size_t)(NCH-1-c)*D_];
    const float* ub = u + ((size_t)b << 10) * D_ + d;
    const float* yr = g_yrow + ((size_t)b << 10) * D_ + d;
    const float* gb = xg + ((size_t)b << 10) * (2*D_) + D_ + d;
    float* ho = hout + ((size_t)b << 10) * D_ + d;
    float cd = cvec[d], ddv = dvec[d];
    float termb[CHL];
    float sb = off_b;
#pragma unroll
    for (int i = CHL-1; i >= 0; i--) {
        int s = c*CHL + i;
        int pos = ((s & 31) << 5) + (s >> 5);
        int tb = L_-1-s;
        sb += ub[(size_t)pos * D_] * bd * g_iap[tb*D_ + d];
        termb[i] = g_ap[tb*D_ + d] * sb;
    }
    float sf = off_f;
#pragma unroll
    for (int i = 0; i < CHL; i++) {
        int s = c*CHL + i;
        int pos = ((s & 31) << 5) + (s >> 5);
        float uraw = ub[(size_t)pos * D_];
        sf += uraw * bd * g_iap[s*D_ + d];
        float vcol = g_ap[s*D_ + d] * sf + termb[i];
        float ysum = yr[(size_t)pos * D_] + vcol;
        float res = 0.25f * cd * ysum + ddv * uraw;
        float gt = gb[(size_t)pos * (2*D_)];
        ho[(size_t)pos * D_] = res * (1.f / (1.f + expf(-gt)));
    }
}

// ---------------- mean pool over the 1024 grid positions ----------------
__global__ void __launch_bounds__(512) pool_kernel(
    const float* __restrict__ h, float* __restrict__ out)
{
    int b = blockIdx.x, d = threadIdx.x;
    const float* p = h + (size_t)b * L_ * D_ + d;
    double acc = 0.0;
    for (int t = 0; t < L_; t++) acc += (double)p[(size_t)t * D_];
    out[b*D_ + d] = (float)(acc * (1.0 / 1024.0));
}

extern "C" void kernel_launch(void* const* d_in, const int* in_sizes, int n_in,
                              void* d_out, int out_size)
{
    const float* tokens = (const float*)d_in[0];
    const float* ipw = (const float*)d_in[1];
    const float* ipb = (const float*)d_in[2];
    const float* nw  = (const float*)d_in[3];
    const float* nb  = (const float*)d_in[4];
    const float* iw  = (const float*)d_in[5];
    const float* ib  = (const float*)d_in[6];
    const float* cw  = (const float*)d_in[7];
    const float* cb  = (const float*)d_in[8];
    const float* al  = (const float*)d_in[9];
    const float* bb  = (const float*)d_in[10];
    const float* cc  = (const float*)d_in[11];
    const float* dd  = (const float*)d_in[12];
    const float* ow  = (const float*)d_in[13];
    const float* ob  = (const float*)d_in[14];
    const float* onw = (const float*)d_in[15];
    const float* onb = (const float*)d_in[16];
    float* out = (float*)d_out;

    float *px, *ph, *pxg, *pu;
    cudaGetSymbolAddress((void**)&px,  g_x);
    cudaGetSymbolAddress((void**)&ph,  g_h);
    cudaGetSymbolAddress((void**)&pxg, g_xg);
    cudaGetSymbolAddress((void**)&pu,  g_u);

    const int GSMEM = (2*128*36 + 2*32*136) * 4;   // 71680 B
    cudaFuncSetAttribute(gemm_tc<0>, cudaFuncAttributeMaxDynamicSharedMemorySize, GSMEM);
    cudaFuncSetAttribute(gemm_tc<1>, cudaFuncAttributeMaxDynamicSharedMemorySize, GSMEM);

    // in_proj: (16384x768)@(768x512)
    gemm_tc<0><<<dim3(D_/128, M_/128), 256, GSMEM>>>(tokens, ipw, ipb, nullptr, px, M_, D_, C_);

    for (int i = 0; i < 4; i++) {
        ln_kernel<<<M_/8, 256>>>(px, nw + i*D_, nb + i*D_, ph);
        gemm_tc<0><<<dim3(2*D_/128, M_/128), 256, GSMEM>>>(
            ph, iw + (size_t)i*D_*2*D_, ib + i*2*D_, nullptr, pxg, M_, 2*D_, D_);
        conv_silu_kernel<<<B_*H_, 512>>>(pxg, cw + (size_t)i*9*D_, cb + i*D_, pu);
        ap_kernel<<<L_, 512>>>(al + i*D_);
        scanA<<<(2*B_*NCH*D_)/256, 256>>>(pu, bb + i*D_);
        scanB<<<(4*B_*D_)/256, 256>>>();
        scanC_row<<<(B_*NCH*D_)/256, 256>>>(pu, bb + i*D_);
        scanC_col<<<(B_*NCH*D_)/256, 256>>>(pu, pxg, bb + i*D_, cc + i*D_, dd + i*D_, ph);
        gemm_tc<1><<<dim3(D_/128, M_/128), 256, GSMEM>>>(
            ph, ow + (size_t)i*D_*D_, ob + i*D_, px, px, M_, D_, D_);
    }

    ln_kernel<<<M_/8, 256>>>(px, onw, onb, ph);
    pool_kernel<<<B_, 512>>>(ph, out);
}

// round 12
// speedup vs baseline: 4.3476x; 1.3514x over previous
#include <cuda_runtime.h>
#include <cuda_fp16.h>
#include <math.h>
#include <stdint.h>

#define B_ 16
#define H_ 32
#define W_ 32
#define D_ 512
#define L_ 1024           // H_*W_
#define C_ 768
#define M_ (B_*L_)        // 16384 rows
#define NCH 32
#define CHL 32

// ---- static scratch (no allocations allowed) ----
__device__ float  g_x [M_*D_];           // residual stream (fp32)
__device__ float  g_xg[M_*2*D_];         // input-proj output (x_in | gate), fp32
__device__ float  g_u [M_*D_];           // conv+silu output / final LN out
__device__ float  g_yrow[M_*D_];         // row-orientation scan sum
__device__ float  g_ap [L_*D_];          // a_pow table (per current block)
__device__ float  g_iap[L_*D_];          // 1/a_pow table
__device__ float  g_cs [4*B_*NCH*D_];    // chunk partial sums [dir][b][chunk][d]
__device__ __half g_hh [M_*D_];          // fp16 GEMM A operand (LN out / gated h)
__device__ __half g_tok[M_*C_];          // fp16 tokens
__device__ __half g_wTh[512*768 + 4*(1024*512 + 512*512)];  // fp16 transposed weights

__device__ __forceinline__ void cpasync16(unsigned saddr, const void* g){
    asm volatile("cp.async.cg.shared.global [%0], [%1], 16;" :: "r"(saddr), "l"(g));
}
__device__ __forceinline__ uint32_t smem_u32(const void* p){
    uint32_t a; asm("{ .reg .u64 t; cvta.to.shared.u64 t, %1; cvt.u32.u64 %0, t; }" : "=r"(a) : "l"(p));
    return a;
}
#define SWZ(o) ((o) ^ (((o) >> 3) & 0x70))

// ---------------- fp16 tensor-core GEMM: 128x128 tile, K-chunk 64, ldmatrix ----------------
// A [M,K] half row-major, BT [N,K] half row-major. Accum fp32.
// MODE 0: C = A@B + bias ; MODE 1: C = R + A@B + bias
template<int MODE>
__global__ void __launch_bounds__(256, 2) gemm_fp16(
    const __half* __restrict__ A, const __half* __restrict__ BT,
    const float* __restrict__ bias, const float* __restrict__ R,
    float* __restrict__ C, int M, int N, int K)
{
    extern __shared__ char smc[];
    uint32_t sb = smem_u32(smc);
    const uint32_t ASZ = 16384, STSZ = 32768;   // A 128x64 half = 16KB; stage = 32KB
    int t = threadIdx.x;
    int lane = t & 31, wid = t >> 5;
    int bm = blockIdx.y << 7, bn = blockIdx.x << 7;
    int warpM = wid >> 2, warpN = wid & 3;       // 2x4 warps, 64x32 tile each
    int tg = lane & 3, gid = lane >> 2;

    float acc[4][4][4];
#pragma unroll
    for (int i = 0; i < 4; i++)
#pragma unroll
        for (int j = 0; j < 4; j++)
#pragma unroll
            for (int k = 0; k < 4; k++) acc[i][j][k] = 0.f;

    const __half* Ab = A  + (size_t)bm * K;
    const __half* Bb = BT + (size_t)bn * K;

    auto issue = [&](int kb, int st) {
        uint32_t sa = sb + st * STSZ;
#pragma unroll
        for (int j = 0; j < 4; j++) {
            int idx = t + 256*j;
            int r = idx >> 3, cc = idx & 7;
            cpasync16(sa + SWZ(r*128 + cc*16), Ab + (size_t)r * K + kb*64 + cc*8);
        }
        uint32_t sbf = sa + ASZ;
#pragma unroll
        for (int j = 0; j < 4; j++) {
            int idx = t + 256*j;
            int r = idx >> 3, cc = idx & 7;
            cpasync16(sbf + SWZ(r*128 + cc*16), Bb + (size_t)r * K + kb*64 + cc*8);
        }
        asm volatile("cp.async.commit_group;");
    };

    // ldmatrix lane-address components (constant across ks)
    int arow = (lane & 15);                         // + m0
    int acb  = (lane >> 4) << 4;                    // + k0b
    int brow = (lane & 7) + ((lane >> 4) << 3);     // + n0
    int bcb  = ((lane >> 3) & 1) << 4;              // + k0b

    int nkb = K >> 6;
    issue(0, 0);
    for (int kb = 0; kb < nkb; kb++) {
        int st = kb & 1;
        if (kb + 1 < nkb) {
            issue(kb + 1, st ^ 1);
            asm volatile("cp.async.wait_group 1;");
        } else {
            asm volatile("cp.async.wait_group 0;");
        }
        __syncthreads();
        uint32_t sa  = sb + st * STSZ;
        uint32_t sbf = sa + ASZ;
#pragma unroll
        for (int ks = 0; ks < 4; ks++) {
            int k0b = ks << 5;                       // 16 halfs = 32 bytes
            uint32_t a[4][4], bq[2][4];
#pragma unroll
            for (int mt = 0; mt < 4; mt++) {
                int m0 = warpM*64 + mt*16;
                uint32_t ad = sa + SWZ((m0 + arow)*128 + k0b + acb);
                asm volatile("ldmatrix.sync.aligned.m8n8.x4.shared.b16 {%0,%1,%2,%3}, [%4];"
                    : "=r"(a[mt][0]), "=r"(a[mt][1]), "=r"(a[mt][2]), "=r"(a[mt][3]) : "r"(ad));
            }
#pragma unroll
            for (int np = 0; np < 2; np++) {
                int n0 = warpN*32 + np*16;
                uint32_t ad = sbf + SWZ((n0 + brow)*128 + k0b + bcb);
                asm volatile("ldmatrix.sync.aligned.m8n8.x4.shared.b16 {%0,%1,%2,%3}, [%4];"
                    : "=r"(bq[np][0]), "=r"(bq[np][1]), "=r"(bq[np][2]), "=r"(bq[np][3]) : "r"(ad));
            }
#pragma unroll
            for (int mt = 0; mt < 4; mt++)
#pragma unroll
                for (int np = 0; np < 2; np++)
#pragma unroll
                    for (int hh = 0; hh < 2; hh++) {
                        int nt = np*2 + hh;
                        asm volatile(
                            "mma.sync.aligned.m16n8k16.row.col.f32.f16.f16.f32 "
                            "{%0,%1,%2,%3}, {%4,%5,%6,%7}, {%8,%9}, {%0,%1,%2,%3};"
                            : "+f"(acc[mt][nt][0]), "+f"(acc[mt][nt][1]),
                              "+f"(acc[mt][nt][2]), "+f"(acc[mt][nt][3])
                            : "r"(a[mt][0]), "r"(a[mt][1]), "r"(a[mt][2]), "r"(a[mt][3]),
                              "r"(bq[np][2*hh]), "r"(bq[np][2*hh+1]));
                    }
        }
        __syncthreads();
    }

    // epilogue (same c-fragment layout as m16n8 tf32)
#pragma unroll
    for (int mt = 0; mt < 4; mt++) {
        int r0 = bm + warpM*64 + mt*16 + gid;
#pragma unroll
        for (int nt = 0; nt < 4; nt++) {
            int col = bn + warpN*32 + nt*8 + 2*tg;
            float b0 = bias[col], b1 = bias[col+1];
            float o0 = acc[mt][nt][0] + b0;
            float o1 = acc[mt][nt][1] + b1;
            float o2 = acc[mt][nt][2] + b0;
            float o3 = acc[mt][nt][3] + b1;
            if (MODE == 1) {
                float2 ra = *(const float2*)(R + (size_t)r0 * N + col);
                float2 rb = *(const float2*)(R + (size_t)(r0+8) * N + col);
                o0 += ra.x; o1 += ra.y; o2 += rb.x; o3 += rb.y;
            }
            *(float2*)(C + (size_t)r0 * N + col)     = make_float2(o0, o1);
            *(float2*)(C + (size_t)(r0+8) * N + col) = make_float2(o2, o3);
        }
    }
}

// ---------------- transpose weights [K,N] -> [N,K], fp16 ----------------
__global__ void __launch_bounds__(256) transpose_h(
    const float* __restrict__ src, __half* __restrict__ dst, int K, int N)
{
    __shared__ float tile[32][33];
    int kx = blockIdx.x * 32, ny = blockIdx.y * 32;
    int tx = threadIdx.x & 31, ty0 = threadIdx.x >> 5;   // 32x8
#pragma unroll
    for (int j = 0; j < 32; j += 8) {
        int ty = ty0 + j;
        tile[ty][tx] = src[(size_t)(kx + ty) * N + ny + tx];
    }
    __syncthreads();
#pragma unroll
    for (int j = 0; j < 32; j += 8) {
        int ty = ty0 + j;
        dst[(size_t)(ny + ty) * K + kx + tx] = __float2half_rn(tile[tx][ty]);
    }
}

// ---------------- tokens -> fp16 ----------------
__global__ void __launch_bounds__(256) tok2half(
    const float* __restrict__ src, __half* __restrict__ dst)
{
    int i = (blockIdx.x * 256 + threadIdx.x) * 4;
    float4 v = *(const float4*)(src + i);
    __half2 h0 = __floats2half2_rn(v.x, v.y);
    __half2 h1 = __floats2half2_rn(v.z, v.w);
    *(__half2*)(dst + i)     = h0;
    *(__half2*)(dst + i + 2) = h1;
}

// ---------------- LayerNorm: one warp per row of 512; HOUT: fp16 output ----------------
template<bool HOUT>
__global__ void __launch_bounds__(256) ln_kernel(
    const float* __restrict__ x, const float* __restrict__ w,
    const float* __restrict__ b, void* __restrict__ outv)
{
    int row  = blockIdx.x * 8 + (threadIdx.x >> 5);
    int lane = threadIdx.x & 31;
    const float* xr = x + (size_t)row * D_;
    float4 v[4];
    float s = 0.f, sq = 0.f;
#pragma unroll
    for (int i = 0; i < 4; i++) {
        v[i] = *(const float4*)(xr + i*128 + lane*4);
        s  += v[i].x + v[i].y + v[i].z + v[i].w;
        sq += v[i].x*v[i].x + v[i].y*v[i].y + v[i].z*v[i].z + v[i].w*v[i].w;
    }
#pragma unroll
    for (int o = 16; o; o >>= 1) {
        s  += __shfl_xor_sync(0xffffffffu, s,  o);
        sq += __shfl_xor_sync(0xffffffffu, sq, o);
    }
    float mu  = s * (1.0f / D_);
    float var = sq * (1.0f / D_) - mu * mu;
    float rs  = rsqrtf(var + 1e-5f);
#pragma unroll
    for (int i = 0; i < 4; i++) {
        int col = i*128 + lane*4;
        float4 wv = *(const float4*)(w + col);
        float4 bv = *(const float4*)(b + col);
        float4 o;
        o.x = (v[i].x - mu) * rs * wv.x + bv.x;
        o.y = (v[i].y - mu) * rs * wv.y + bv.y;
        o.z = (v[i].z - mu) * rs * wv.z + bv.z;
        o.w = (v[i].w - mu) * rs * wv.w + bv.w;
        if (HOUT) {
            __half* orow = (__half*)outv + (size_t)row * D_;
            *(__half2*)(orow + col)     = __floats2half2_rn(o.x, o.y);
            *(__half2*)(orow + col + 2) = __floats2half2_rn(o.z, o.w);
        } else {
            float* orow = (float*)outv + (size_t)row * D_;
            *(float4*)(orow + col) = o;
        }
    }
}

// ---------------- depthwise 3x3 conv + bias + SiLU, register-shifted window ----------------
__global__ void __launch_bounds__(512) conv_silu_kernel(
    const float* __restrict__ xg, const float* __restrict__ cw,
    const float* __restrict__ cb, float* __restrict__ u)
{
    int bh = blockIdx.x;              // b*32 + h
    int d = threadIdx.x;
    int h = bh & 31, b = bh >> 5;
    float Wk[3][3];
#pragma unroll
    for (int r = 0; r < 3; r++)
#pragma unroll
        for (int c = 0; c < 3; c++) Wk[r][c] = cw[(r*3 + c)*D_ + d];
    float bias = cb[d];
    const float* base = xg + ((size_t)(b << 10)) * (2*D_) + d;
    bool hm = h > 0, hp = h < 31;
    float xm0 = 0.f, xm1 = 0.f, xm2 = 0.f;
    float xc0 = hm ? base[(size_t)((h-1)*32)*(2*D_)] : 0.f;
    float xc1 =      base[(size_t)( h   *32)*(2*D_)];
    float xc2 = hp ? base[(size_t)((h+1)*32)*(2*D_)] : 0.f;
    float* uo = u + (size_t)((b << 10) + (h << 5)) * D_ + d;
#pragma unroll 4
    for (int w = 0; w < 32; w++) {
        float xp0 = 0.f, xp1 = 0.f, xp2 = 0.f;
        if (w < 31) {
            xp0 = hm ? base[(size_t)((h-1)*32 + w+1)*(2*D_)] : 0.f;
            xp1 =      base[(size_t)( h   *32 + w+1)*(2*D_)];
            xp2 = hp ? base[(size_t)((h+1)*32 + w+1)*(2*D_)] : 0.f;
        }
        float acc = bias;
        acc += xm0*Wk[0][0] + xc0*Wk[0][1] + xp0*Wk[0][2];
        acc += xm1*Wk[1][0] + xc1*Wk[1][1] + xp1*Wk[1][2];
        acc += xm2*Wk[2][0] + xc2*Wk[2][1] + xp2*Wk[2][2];
        uo[(size_t)w * D_] = acc / (1.f + expf(-acc));
        xm0 = xc0; xm1 = xc1; xm2 = xc2;
        xc0 = xp0; xc1 = xp1; xc2 = xp2;
    }
}

// ---------------- a_pow tables (replicates clamped log-domain form) ----------------
__global__ void __launch_bounds__(512) ap_kernel(const float* __restrict__ alog)
{
    int d = threadIdx.x, t = blockIdx.x;
    float a = 1.f / (1.f + expf(-alog[d]));
    a = fminf(fmaxf(a, 1e-4f), 1.f - 1e-4f);
    float ap = fmaxf(expf((float)t * logf(a)), 1e-20f);
    g_ap [t*D_ + d] = ap;
    g_iap[t*D_ + d] = 1.f / ap;
}

// ---------------- pass A: per-chunk fwd+bwd partial sums, both orientations ----------------
__global__ void __launch_bounds__(256) scanA(
    const float* __restrict__ u, const float* __restrict__ bvec)
{
    int tid = blockIdx.x * 256 + threadIdx.x;   // 2*16*32*512 = 524288
    int d      = tid & 511;
    int c      = (tid >> 9) & 31;
    int b      = (tid >> 14) & 15;
    int orient = tid >> 18;                      // 0=row, 1=col
    float bd = bvec[d];
    const float* ub = u + ((size_t)b << 10) * D_ + d;
    float sf = 0.f, sb = 0.f;
#pragma unroll
    for (int i = 0; i < CHL; i++) {
        int s = c*CHL + i;                       // seq index (fwd)
        int pos = orient ? ((s & 31) << 5) + (s >> 5) : s;
        float uv = ub[(size_t)pos * D_] * bd;
        sf += uv * g_iap[s*D_ + d];
        sb += uv * g_iap[(L_-1-s)*D_ + d];
    }
    size_t dstr = (size_t)B_*NCH*D_;
    size_t base = (size_t)(orient*2) * dstr + ((size_t)b*NCH)*D_ + d;
    g_cs[base + (size_t)c*D_] = sf;
    g_cs[base + dstr + (size_t)(NCH-1-c)*D_] = sb;
}

// ---------------- pass B: exclusive prefix over 32 chunk sums per direction ----------------
__global__ void __launch_bounds__(256) scanB()
{
    int tid = blockIdx.x * 256 + threadIdx.x;   // 4*16*512 = 32768
    int d = tid & 511;
    int b = (tid >> 9) & 15;
    int dir = tid >> 13;
    size_t base = (((size_t)dir * B_ + b) * NCH) * D_ + d;
    float s = 0.f;
#pragma unroll
    for (int c = 0; c < NCH; c++) {
        float v = g_cs[base + (size_t)c * D_];
        g_cs[base + (size_t)c * D_] = s;
        s += v;
    }
}

// ---------------- pass C row: fwd+bwd replay, single store of summed terms ----------------
__global__ void __launch_bounds__(256) scanC_row(
    const float* __restrict__ u, const float* __restrict__ bvec)
{
    int tid = blockIdx.x * 256 + threadIdx.x;   // 16*32*512 = 262144
    int d = tid & 511;
    int c = (tid >> 9) & 31;
    int b = tid >> 14;
    float bd = bvec[d];
    size_t dstr = (size_t)B_*NCH*D_;
    size_t csb = ((size_t)b*NCH)*D_ + d;
    float off_f = g_cs[csb + (size_t)c*D_];
    float off_b = g_cs[dstr + csb + (size_t)(NCH-1-c)*D_];
    const float* ub = u + ((size_t)b << 10) * D_ + d;
    float* yr = g_yrow + ((size_t)b << 10) * D_ + d;
    float termb[CHL];
    float sb = off_b;
#pragma unroll
    for (int i = CHL-1; i >= 0; i--) {
        int s = c*CHL + i;
        int tb = L_-1-s;
        sb += ub[(size_t)s * D_] * bd * g_iap[tb*D_ + d];
        termb[i] = g_ap[tb*D_ + d] * sb;
    }
    float sf = off_f;
#pragma unroll
    for (int i = 0; i < CHL; i++) {
        int s = c*CHL + i;
        sf += ub[(size_t)s * D_] * bd * g_iap[s*D_ + d];
        yr[(size_t)s * D_] = g_ap[s*D_ + d] * sf + termb[i];
    }
}

// ---------------- pass C col + combine + gate: writes fp16 GEMM A operand ----------------
__global__ void __launch_bounds__(256) scanC_col(
    const float* __restrict__ u, const float* __restrict__ xg,
    const float* __restrict__ bvec, const float* __restrict__ cvec,
    const float* __restrict__ dvec, __half* __restrict__ hout)
{
    int tid = blockIdx.x * 256 + threadIdx.x;   // 262144
    int d = tid & 511;
    int c = (tid >> 9) & 31;
    int b = tid >> 14;
    float bd = bvec[d];
    size_t dstr = (size_t)B_*NCH*D_;
    size_t csb = ((size_t)b*NCH)*D_ + d;
    float off_f = g_cs[2*dstr + csb + (size_t)c*D_];
    float off_b = g_cs[3*dstr + csb + (size_t)(NCH-1-c)*D_];
    const float* ub = u + ((size_t)b << 10) * D_ + d;
    const float* yr = g_yrow + ((size_t)b << 10) * D_ + d;
    const float* gb = xg + ((size_t)b << 10) * (2*D_) + D_ + d;
    __half* ho = hout + ((size_t)b << 10) * D_ + d;
    float cd = cvec[d], ddv = dvec[d];
    float termb[CHL];
    float sb = off_b;
#pragma unroll
    for (int i = CHL-1; i >= 0; i--) {
        int s = c*CHL + i;
        int pos = ((s & 31) << 5) + (s >> 5);
        int tb = L_-1-s;
        sb += ub[(size_t)pos * D_] * bd * g_iap[tb*D_ + d];
        termb[i] = g_ap[tb*D_ + d] * sb;
    }
    float sf = off_f;
#pragma unroll
    for (int i = 0; i < CHL; i++) {
        int s = c*CHL + i;
        int pos = ((s & 31) << 5) + (s >> 5);
        float uraw = ub[(size_t)pos * D_];
        sf += uraw * bd * g_iap[s*D_ + d];
        float vcol = g_ap[s*D_ + d] * sf + termb[i];
        float ysum = yr[(size_t)pos * D_] + vcol;
        float res = 0.25f * cd * ysum + ddv * uraw;
        float gt = gb[(size_t)pos * (2*D_)];
        ho[(size_t)pos * D_] = __float2half_rn(res * (1.f / (1.f + expf(-gt))));
    }
}

// ---------------- mean pool over the 1024 grid positions ----------------
__global__ void __launch_bounds__(512) pool_kernel(
    const float* __restrict__ h, float* __restrict__ out)
{
    int b = blockIdx.x, d = threadIdx.x;
    const float* p = h + (size_t)b * L_ * D_ + d;
    double acc = 0.0;
    for (int t = 0; t < L_; t++) acc += (double)p[(size_t)t * D_];
    out[b*D_ + d] = (float)(acc * (1.0 / 1024.0));
}

extern "C" void kernel_launch(void* const* d_in, const int* in_sizes, int n_in,
                              void* d_out, int out_size)
{
    const float* tokens = (const float*)d_in[0];
    const float* ipw = (const float*)d_in[1];
    const float* ipb = (const float*)d_in[2];
    const float* nw  = (const float*)d_in[3];
    const float* nb  = (const float*)d_in[4];
    const float* iw  = (const float*)d_in[5];
    const float* ib  = (const float*)d_in[6];
    const float* cw  = (const float*)d_in[7];
    const float* cb  = (const float*)d_in[8];
    const float* al  = (const float*)d_in[9];
    const float* bb  = (const float*)d_in[10];
    const float* cc  = (const float*)d_in[11];
    const float* dd  = (const float*)d_in[12];
    const float* ow  = (const float*)d_in[13];
    const float* ob  = (const float*)d_in[14];
    const float* onw = (const float*)d_in[15];
    const float* onb = (const float*)d_in[16];
    float* out = (float*)d_out;

    float *px, *pxg, *pu;
    __half *phh, *ptok, *pwTh;
    cudaGetSymbolAddress((void**)&px,   g_x);
    cudaGetSymbolAddress((void**)&pxg,  g_xg);
    cudaGetSymbolAddress((void**)&pu,   g_u);
    cudaGetSymbolAddress((void**)&phh,  g_hh);
    cudaGetSymbolAddress((void**)&ptok, g_tok);
    cudaGetSymbolAddress((void**)&pwTh, g_wTh);

    __half* ipwT = pwTh;                                  // [512,768]
    __half* iwT0 = pwTh + 512*768;                        // 4 x [1024,512]
    __half* owT0 = pwTh + 512*768 + 4*1024*512;           // 4 x [512,512]

    const int GSMEM = 2 * 32768;   // 65536 B
    cudaFuncSetAttribute(gemm_fp16<0>, cudaFuncAttributeMaxDynamicSharedMemorySize, GSMEM);
    cudaFuncSetAttribute(gemm_fp16<1>, cudaFuncAttributeMaxDynamicSharedMemorySize, GSMEM);

    // weight transposes (fp16), token conversion
    transpose_h<<<dim3(C_/32, D_/32), 256>>>(ipw, ipwT, C_, D_);
    for (int i = 0; i < 4; i++) {
        transpose_h<<<dim3(D_/32, 2*D_/32), 256>>>(iw + (size_t)i*D_*2*D_, iwT0 + (size_t)i*2*D_*D_, D_, 2*D_);
        transpose_h<<<dim3(D_/32, D_/32), 256>>>(ow + (size_t)i*D_*D_, owT0 + (size_t)i*D_*D_, D_, D_);
    }
    tok2half<<<(M_*C_)/1024, 256>>>(tokens, ptok);

    // in_proj: (16384x768)@(768x512)
    gemm_fp16<0><<<dim3(D_/128, M_/128), 256, GSMEM>>>(ptok, ipwT, ipb, nullptr, px, M_, D_, C_);

    for (int i = 0; i < 4; i++) {
        ln_kernel<true><<<M_/8, 256>>>(px, nw + i*D_, nb + i*D_, phh);
        gemm_fp16<0><<<dim3(2*D_/128, M_/128), 256, GSMEM>>>(
            phh, iwT0 + (size_t)i*2*D_*D_, ib + i*2*D_, nullptr, pxg, M_, 2*D_, D_);
        conv_silu_kernel<<<B_*H_, 512>>>(pxg, cw + (size_t)i*9*D_, cb + i*D_, pu);
        ap_kernel<<<L_, 512>>>(al + i*D_);
        scanA<<<(2*B_*NCH*D_)/256, 256>>>(pu, bb + i*D_);
        scanB<<<(4*B_*D_)/256, 256>>>();
        scanC_row<<<(B_*NCH*D_)/256, 256>>>(pu, bb + i*D_);
        scanC_col<<<(B_*NCH*D_)/256, 256>>>(pu, pxg, bb + i*D_, cc + i*D_, dd + i*D_, phh);
        gemm_fp16<1><<<dim3(D_/128, M_/128), 256, GSMEM>>>(
            phh, owT0 + (size_t)i*D_*D_, ob + i*D_, px, px, M_, D_, D_);
    }

    ln_kernel<false><<<M_/8, 256>>>(px, onw, onb, pu);
    pool_kernel<<<B_, 512>>>(pu, out);
}

// round 16
// speedup vs baseline: 4.6232x; 1.0634x over previous
#include <cuda_runtime.h>
#include <cuda_fp16.h>
#include <math.h>
#include <stdint.h>

#define B_ 16
#define H_ 32
#define W_ 32
#define D_ 512
#define L_ 1024           // H_*W_
#define C_ 768
#define M_ (B_*L_)        // 16384 rows
#define NCH 32
#define CHL 32

// ---- static scratch (no allocations allowed) ----
__device__ float  g_x [M_*D_];           // residual stream (fp32)
__device__ float  g_xg[M_*2*D_];         // input-proj output (x_in | gate), fp32
__device__ float  g_u [M_*D_];           // conv+silu output / final LN out
__device__ float  g_yrow[M_*D_];         // row-orientation scan sum
__device__ float  g_ap [4*L_*D_];        // a_pow tables (all 4 blocks)
__device__ float  g_iap[4*L_*D_];        // 1/a_pow tables
__device__ float  g_cs [4*B_*NCH*D_];    // chunk partial sums [dir][b][chunk][d]
__device__ __half g_hh [M_*D_];          // fp16 GEMM A operand (LN out / gated h)
__device__ __half g_tok[M_*C_];          // fp16 tokens
__device__ __half g_wTh[512*768 + 4*(1024*512 + 512*512)];  // fp16 transposed weights

__device__ __forceinline__ void cpasync16(unsigned saddr, const void* g){
    asm volatile("cp.async.cg.shared.global [%0], [%1], 16;" :: "r"(saddr), "l"(g));
}
__device__ __forceinline__ uint32_t smem_u32(const void* p){
    uint32_t a; asm("{ .reg .u64 t; cvta.to.shared.u64 t, %1; cvt.u32.u64 %0, t; }" : "=r"(a) : "l"(p));
    return a;
}
#define SWZ(o) ((o) ^ (((o) >> 3) & 0x70))

// ---------------- fp16 tensor-core GEMM: 128x128 tile, K-chunk 64, 3-stage ----------------
// A [M,K] half row-major, BT [N,K] half row-major. Accum fp32.
// MODE 0: C = A@B + bias ; MODE 1: C = R + A@B + bias
template<int MODE>
__global__ void __launch_bounds__(256, 2) gemm_fp16(
    const __half* __restrict__ A, const __half* __restrict__ BT,
    const float* __restrict__ bias, const float* __restrict__ R,
    float* __restrict__ C, int M, int N, int K)
{
    extern __shared__ char smc[];
    uint32_t sb = smem_u32(smc);
    const uint32_t ASZ = 16384, STSZ = 32768;   // A 128x64 half = 16KB; stage = 32KB
    int t = threadIdx.x;
    int lane = t & 31, wid = t >> 5;
    int bm = blockIdx.y << 7, bn = blockIdx.x << 7;
    int warpM = wid >> 2, warpN = wid & 3;       // 2x4 warps, 64x32 tile each
    int tg = lane & 3, gid = lane >> 2;

    float acc[4][4][4];
#pragma unroll
    for (int i = 0; i < 4; i++)
#pragma unroll
        for (int j = 0; j < 4; j++)
#pragma unroll
            for (int k = 0; k < 4; k++) acc[i][j][k] = 0.f;

    const __half* Ab = A  + (size_t)bm * K;
    const __half* Bb = BT + (size_t)bn * K;

    auto issue = [&](int kb, int st) {
        uint32_t sa = sb + st * STSZ;
#pragma unroll
        for (int j = 0; j < 4; j++) {
            int idx = t + 256*j;
            int r = idx >> 3, cc = idx & 7;
            cpasync16(sa + SWZ(r*128 + cc*16), Ab + (size_t)r * K + kb*64 + cc*8);
        }
        uint32_t sbf = sa + ASZ;
#pragma unroll
        for (int j = 0; j < 4; j++) {
            int idx = t + 256*j;
            int r = idx >> 3, cc = idx & 7;
            cpasync16(sbf + SWZ(r*128 + cc*16), Bb + (size_t)r * K + kb*64 + cc*8);
        }
        asm volatile("cp.async.commit_group;");
    };

    // ldmatrix lane-address components (constant across ks)
    int arow = (lane & 15);                         // + m0
    int acb  = (lane >> 4) << 4;                    // + k0b
    int brow = (lane & 7) + ((lane >> 4) << 3);     // + n0
    int bcb  = ((lane >> 3) & 1) << 4;              // + k0b

    int nkb = K >> 6;
    issue(0, 0);
    issue(1, 1);
    for (int kb = 0; kb < nkb; kb++) {
        if (kb + 1 < nkb) asm volatile("cp.async.wait_group 1;");
        else              asm volatile("cp.async.wait_group 0;");
        __syncthreads();              // stage kb visible; all warps done with stage kb-1
        int nx = kb + 2;
        if (nx < nkb) issue(nx, nx % 3);   // slot (kb-1)%3 — retired last iteration
        int st = kb % 3;
        uint32_t sa  = sb + st * STSZ;
        uint32_t sbf = sa + ASZ;
#pragma unroll
        for (int ks = 0; ks < 4; ks++) {
            int k0b = ks << 5;                       // 16 halfs = 32 bytes
            uint32_t a[4][4], bq[2][4];
#pragma unroll
            for (int mt = 0; mt < 4; mt++) {
                int m0 = warpM*64 + mt*16;
                uint32_t ad = sa + SWZ((m0 + arow)*128 + k0b + acb);
                asm volatile("ldmatrix.sync.aligned.m8n8.x4.shared.b16 {%0,%1,%2,%3}, [%4];"
                    : "=r"(a[mt][0]), "=r"(a[mt][1]), "=r"(a[mt][2]), "=r"(a[mt][3]) : "r"(ad));
            }
#pragma unroll
            for (int np = 0; np < 2; np++) {
                int n0 = warpN*32 + np*16;
                uint32_t ad = sbf + SWZ((n0 + brow)*128 + k0b + bcb);
                asm volatile("ldmatrix.sync.aligned.m8n8.x4.shared.b16 {%0,%1,%2,%3}, [%4];"
                    : "=r"(bq[np][0]), "=r"(bq[np][1]), "=r"(bq[np][2]), "=r"(bq[np][3]) : "r"(ad));
            }
#pragma unroll
            for (int mt = 0; mt < 4; mt++)
#pragma unroll
                for (int np = 0; np < 2; np++)
#pragma unroll
                    for (int hh = 0; hh < 2; hh++) {
                        int nt = np*2 + hh;
                        asm volatile(
                            "mma.sync.aligned.m16n8k16.row.col.f32.f16.f16.f32 "
                            "{%0,%1,%2,%3}, {%4,%5,%6,%7}, {%8,%9}, {%0,%1,%2,%3};"
                            : "+f"(acc[mt][nt][0]), "+f"(acc[mt][nt][1]),
                              "+f"(acc[mt][nt][2]), "+f"(acc[mt][nt][3])
                            : "r"(a[mt][0]), "r"(a[mt][1]), "r"(a[mt][2]), "r"(a[mt][3]),
                              "r"(bq[np][2*hh]), "r"(bq[np][2*hh+1]));
                    }
        }
    }

    // epilogue
#pragma unroll
    for (int mt = 0; mt < 4; mt++) {
        int r0 = bm + warpM*64 + mt*16 + gid;
#pragma unroll
        for (int nt = 0; nt < 4; nt++) {
            int col = bn + warpN*32 + nt*8 + 2*tg;
            float b0 = bias[col], b1 = bias[col+1];
            float o0 = acc[mt][nt][0] + b0;
            float o1 = acc[mt][nt][1] + b1;
            float o2 = acc[mt][nt][2] + b0;
            float o3 = acc[mt][nt][3] + b1;
            if (MODE == 1) {
                float2 ra = *(const float2*)(R + (size_t)r0 * N + col);
                float2 rb = *(const float2*)(R + (size_t)(r0+8) * N + col);
                o0 += ra.x; o1 += ra.y; o2 += rb.x; o3 += rb.y;
            }
            *(float2*)(C + (size_t)r0 * N + col)     = make_float2(o0, o1);
            *(float2*)(C + (size_t)(r0+8) * N + col) = make_float2(o2, o3);
        }
    }
}

// ---------------- transpose weights [K,N] -> [N,K], fp16 ----------------
__global__ void __launch_bounds__(256) transpose_h(
    const float* __restrict__ src, __half* __restrict__ dst, int K, int N)
{
    __shared__ float tile[32][33];
    int kx = blockIdx.x * 32, ny = blockIdx.y * 32;
    int tx = threadIdx.x & 31, ty0 = threadIdx.x >> 5;   // 32x8
#pragma unroll
    for (int j = 0; j < 32; j += 8) {
        int ty = ty0 + j;
        tile[ty][tx] = src[(size_t)(kx + ty) * N + ny + tx];
    }
    __syncthreads();
#pragma unroll
    for (int j = 0; j < 32; j += 8) {
        int ty = ty0 + j;
        dst[(size_t)(ny + ty) * K + kx + tx] = __float2half_rn(tile[tx][ty]);
    }
}

// ---------------- tokens -> fp16 ----------------
__global__ void __launch_bounds__(256) tok2half(
    const float* __restrict__ src, __half* __restrict__ dst)
{
    int i = (blockIdx.x * 256 + threadIdx.x) * 4;
    float4 v = *(const float4*)(src + i);
    *(__half2*)(dst + i)     = __floats2half2_rn(v.x, v.y);
    *(__half2*)(dst + i + 2) = __floats2half2_rn(v.z, v.w);
}

// ---------------- LayerNorm: one warp per row of 512; HOUT: fp16 output ----------------
template<bool HOUT>
__global__ void __launch_bounds__(256) ln_kernel(
    const float* __restrict__ x, const float* __restrict__ w,
    const float* __restrict__ b, void* __restrict__ outv)
{
    int row  = blockIdx.x * 8 + (threadIdx.x >> 5);
    int lane = threadIdx.x & 31;
    const float* xr = x + (size_t)row * D_;
    float4 v[4];
    float s = 0.f, sq = 0.f;
#pragma unroll
    for (int i = 0; i < 4; i++) {
        v[i] = *(const float4*)(xr + i*128 + lane*4);
        s  += v[i].x + v[i].y + v[i].z + v[i].w;
        sq += v[i].x*v[i].x + v[i].y*v[i].y + v[i].z*v[i].z + v[i].w*v[i].w;
    }
#pragma unroll
    for (int o = 16; o; o >>= 1) {
        s  += __shfl_xor_sync(0xffffffffu, s,  o);
        sq += __shfl_xor_sync(0xffffffffu, sq, o);
    }
    float mu  = s * (1.0f / D_);
    float var = sq * (1.0f / D_) - mu * mu;
    float rs  = rsqrtf(var + 1e-5f);
#pragma unroll
    for (int i = 0; i < 4; i++) {
        int col = i*128 + lane*4;
        float4 wv = *(const float4*)(w + col);
        float4 bv = *(const float4*)(b + col);
        float4 o;
        o.x = (v[i].x - mu) * rs * wv.x + bv.x;
        o.y = (v[i].y - mu) * rs * wv.y + bv.y;
        o.z = (v[i].z - mu) * rs * wv.z + bv.z;
        o.w = (v[i].w - mu) * rs * wv.w + bv.w;
        if (HOUT) {
            __half* orow = (__half*)outv + (size_t)row * D_;
            *(__half2*)(orow + col)     = __floats2half2_rn(o.x, o.y);
            *(__half2*)(orow + col + 2) = __floats2half2_rn(o.z, o.w);
        } else {
            float* orow = (float*)outv + (size_t)row * D_;
            *(float4*)(orow + col) = o;
        }
    }
}

// ---------------- depthwise 3x3 conv + bias + SiLU: float2 per thread ----------------
__global__ void __launch_bounds__(256) conv_silu_kernel(
    const float* __restrict__ xg, const float* __restrict__ cw,
    const float* __restrict__ cb, float* __restrict__ u)
{
    int bh = blockIdx.x;              // b*32 + h
    int d = threadIdx.x * 2;          // 2 channels per thread
    int h = bh & 31, b = bh >> 5;
    float2 Wk[3][3];
#pragma unroll
    for (int r = 0; r < 3; r++)
#pragma unroll
        for (int c = 0; c < 3; c++) Wk[r][c] = *(const float2*)(cw + (r*3 + c)*D_ + d);
    float2 bias = *(const float2*)(cb + d);
    const float* base = xg + ((size_t)(b << 10)) * (2*D_) + d;
    bool hm = h > 0, hp = h < 31;
    const float2 z2 = make_float2(0.f, 0.f);
    float2 xm0 = z2, xm1 = z2, xm2 = z2;
    float2 xc0 = hm ? *(const float2*)(base + (size_t)((h-1)*32)*(2*D_)) : z2;
    float2 xc1 =      *(const float2*)(base + (size_t)( h   *32)*(2*D_));
    float2 xc2 = hp ? *(const float2*)(base + (size_t)((h+1)*32)*(2*D_)) : z2;
    float* uo = u + (size_t)((b << 10) + (h << 5)) * D_ + d;
#pragma unroll 4
    for (int w = 0; w < 32; w++) {
        float2 xp0 = z2, xp1 = z2, xp2 = z2;
        if (w < 31) {
            xp0 = hm ? *(const float2*)(base + (size_t)((h-1)*32 + w+1)*(2*D_)) : z2;
            xp1 =      *(const float2*)(base + (size_t)( h   *32 + w+1)*(2*D_));
            xp2 = hp ? *(const float2*)(base + (size_t)((h+1)*32 + w+1)*(2*D_)) : z2;
        }
        float ax = bias.x, ay = bias.y;
        ax += xm0.x*Wk[0][0].x + xc0.x*Wk[0][1].x + xp0.x*Wk[0][2].x;
        ay += xm0.y*Wk[0][0].y + xc0.y*Wk[0][1].y + xp0.y*Wk[0][2].y;
        ax += xm1.x*Wk[1][0].x + xc1.x*Wk[1][1].x + xp1.x*Wk[1][2].x;
        ay += xm1.y*Wk[1][0].y + xc1.y*Wk[1][1].y + xp1.y*Wk[1][2].y;
        ax += xm2.x*Wk[2][0].x + xc2.x*Wk[2][1].x + xp2.x*Wk[2][2].x;
        ay += xm2.y*Wk[2][0].y + xc2.y*Wk[2][1].y + xp2.y*Wk[2][2].y;
        float2 o;
        o.x = ax / (1.f + expf(-ax));
        o.y = ay / (1.f + expf(-ay));
        *(float2*)(uo + (size_t)w * D_) = o;
        xm0 = xc0; xm1 = xc1; xm2 = xc2;
        xc0 = xp0; xc1 = xp1; xc2 = xp2;
    }
}

// ---------------- a_pow tables for ALL 4 blocks (clamped log-domain form) ----------------
__global__ void __launch_bounds__(512) ap_all_kernel(const float* __restrict__ alog)
{
    int d = threadIdx.x;
    int t = blockIdx.x & (L_ - 1);
    int blk = blockIdx.x >> 10;
    float a = 1.f / (1.f + expf(-alog[blk*D_ + d]));
    a = fminf(fmaxf(a, 1e-4f), 1.f - 1e-4f);
    float ap = fmaxf(expf((float)t * logf(a)), 1e-20f);
    size_t off = (size_t)blk * L_ * D_ + t*D_ + d;
    g_ap [off] = ap;
    g_iap[off] = 1.f / ap;
}

// ---------------- pass A: per-chunk fwd+bwd partial sums, both orientations ----------------
__global__ void __launch_bounds__(256) scanA(
    const float* __restrict__ u, const float* __restrict__ bvec,
    const float* __restrict__ iap)
{
    int tid = blockIdx.x * 256 + threadIdx.x;   // 2*16*32*512 = 524288
    int d      = tid & 511;
    int c      = (tid >> 9) & 31;
    int b      = (tid >> 14) & 15;
    int orient = tid >> 18;                      // 0=row, 1=col
    float bd = bvec[d];
    const float* ub = u + ((size_t)b << 10) * D_ + d;
    float sf = 0.f, sb = 0.f;
#pragma unroll
    for (int i = 0; i < CHL; i++) {
        int s = c*CHL + i;                       // seq index (fwd)
        int pos = orient ? ((s & 31) << 5) + (s >> 5) : s;
        float uv = ub[(size_t)pos * D_] * bd;
        sf += uv * iap[s*D_ + d];
        sb += uv * iap[(L_-1-s)*D_ + d];
    }
    size_t dstr = (size_t)B_*NCH*D_;
    size_t base = (size_t)(orient*2) * dstr + ((size_t)b*NCH)*D_ + d;
    g_cs[base + (size_t)c*D_] = sf;
    g_cs[base + dstr + (size_t)(NCH-1-c)*D_] = sb;
}

// ---------------- pass B: exclusive prefix over 32 chunk sums per direction ----------------
__global__ void __launch_bounds__(256) scanB()
{
    int tid = blockIdx.x * 256 + threadIdx.x;   // 4*16*512 = 32768
    int d = tid & 511;
    int b = (tid >> 9) & 15;
    int dir = tid >> 13;
    size_t base = (((size_t)dir * B_ + b) * NCH) * D_ + d;
    float s = 0.f;
#pragma unroll
    for (int c = 0; c < NCH; c++) {
        float v = g_cs[base + (size_t)c * D_];
        g_cs[base + (size_t)c * D_] = s;
        s += v;
    }
}

// ---------------- pass C row: fwd+bwd replay, single store of summed terms ----------------
__global__ void __launch_bounds__(256) scanC_row(
    const float* __restrict__ u, const float* __restrict__ bvec,
    const float* __restrict__ ap, const float* __restrict__ iap)
{
    int tid = blockIdx.x * 256 + threadIdx.x;   // 16*32*512 = 262144
    int d = tid & 511;
    int c = (tid >> 9) & 31;
    int b = tid >> 14;
    float bd = bvec[d];
    size_t dstr = (size_t)B_*NCH*D_;
    size_t csb = ((size_t)b*NCH)*D_ + d;
    float off_f = g_cs[csb + (size_t)c*D_];
    float off_b = g_cs[dstr + csb + (size_t)(NCH-1-c)*D_];
    const float* ub = u + ((size_t)b << 10) * D_ + d;
    float* yr = g_yrow + ((size_t)b << 10) * D_ + d;
    float termb[CHL];
    float sb = off_b;
#pragma unroll
    for (int i = CHL-1; i >= 0; i--) {
        int s = c*CHL + i;
        int tb = L_-1-s;
        sb += ub[(size_t)s * D_] * bd * iap[tb*D_ + d];
        termb[i] = ap[tb*D_ + d] * sb;
    }
    float sf = off_f;
#pragma unroll
    for (int i = 0; i < CHL; i++) {
        int s = c*CHL + i;
        sf += ub[(size_t)s * D_] * bd * iap[s*D_ + d];
        yr[(size_t)s * D_] = ap[s*D_ + d] * sf + termb[i];
    }
}

// ---------------- pass C col + combine + gate: writes fp16 GEMM A operand ----------------
__global__ void __launch_bounds__(256) scanC_col(
    const float* __restrict__ u, const float* __restrict__ xg,
    const float* __restrict__ bvec, const float* __restrict__ cvec,
    const float* __restrict__ dvec, __half* __restrict__ hout,
    const float* __restrict__ ap, const float* __restrict__ iap)
{
    int tid = blockIdx.x * 256 + threadIdx.x;   // 262144
    int d = tid & 511;
    int c = (tid >> 9) & 31;
    int b = tid >> 14;
    float bd = bvec[d];
    size_t dstr = (size_t)B_*NCH*D_;
    size_t csb = ((size_t)b*NCH)*D_ + d;
    float off_f = g_cs[2*dstr + csb + (size_t)c*D_];
    float off_b = g_cs[3*dstr + csb + (size_t)(NCH-1-c)*D_];
    const float* ub = u + ((size_t)b << 10) * D_ + d;
    const float* yr = g_yrow + ((size_t)b << 10) * D_ + d;
    const float* gb = xg + ((size_t)b << 10) * (2*D_) + D_ + d;
    __half* ho = hout + ((size_t)b << 10) * D_ + d;
    float cd = cvec[d], ddv = dvec[d];
    float termb[CHL];
    float sb = off_b;
#pragma unroll
    for (int i = CHL-1; i >= 0; i--) {
        int s = c*CHL + i;
        int pos = ((s & 31) << 5) + (s >> 5);
        int tb = L_-1-s;
        sb += ub[(size_t)pos * D_] * bd * iap[tb*D_ + d];
        termb[i] = ap[tb*D_ + d] * sb;
    }
    float sf = off_f;
#pragma unroll
    for (int i = 0; i < CHL; i++) {
        int s = c*CHL + i;
        int pos = ((s & 31) << 5) + (s >> 5);
        float uraw = ub[(size_t)pos * D_];
        sf += uraw * bd * iap[s*D_ + d];
        float vcol = ap[s*D_ + d] * sf + termb[i];
        float ysum = yr[(size_t)pos * D_] + vcol;
        float res = 0.25f * cd * ysum + ddv * uraw;
        float gt = gb[(size_t)pos * (2*D_)];
        ho[(size_t)pos * D_] = __float2half_rn(res * (1.f / (1.f + expf(-gt))));
    }
}

// ---------------- mean pool over the 1024 grid positions ----------------
__global__ void __launch_bounds__(512) pool_kernel(
    const float* __restrict__ h, float* __restrict__ out)
{
    int b = blockIdx.x, d = threadIdx.x;
    const float* p = h + (size_t)b * L_ * D_ + d;
    double acc = 0.0;
    for (int t = 0; t < L_; t++) acc += (double)p[(size_t)t * D_];
    out[b*D_ + d] = (float)(acc * (1.0 / 1024.0));
}

extern "C" void kernel_launch(void* const* d_in, const int* in_sizes, int n_in,
                              void* d_out, int out_size)
{
    const float* tokens = (const float*)d_in[0];
    const float* ipw = (const float*)d_in[1];
    const float* ipb = (const float*)d_in[2];
    const float* nw  = (const float*)d_in[3];
    const float* nb  = (const float*)d_in[4];
    const float* iw  = (const float*)d_in[5];
    const float* ib  = (const float*)d_in[6];
    const float* cw  = (const float*)d_in[7];
    const float* cb  = (const float*)d_in[8];
    const float* al  = (const float*)d_in[9];
    const float* bb  = (const float*)d_in[10];
    const float* cc  = (const float*)d_in[11];
    const float* dd  = (const float*)d_in[12];
    const float* ow  = (const float*)d_in[13];
    const float* ob  = (const float*)d_in[14];
    const float* onw = (const float*)d_in[15];
    const float* onb = (const float*)d_in[16];
    float* out = (float*)d_out;

    float *px, *pxg, *pu, *pap, *piap;
    __half *phh, *ptok, *pwTh;
    cudaGetSymbolAddress((void**)&px,   g_x);
    cudaGetSymbolAddress((void**)&pxg,  g_xg);
    cudaGetSymbolAddress((void**)&pu,   g_u);
    cudaGetSymbolAddress((void**)&pap,  g_ap);
    cudaGetSymbolAddress((void**)&piap, g_iap);
    cudaGetSymbolAddress((void**)&phh,  g_hh);
    cudaGetSymbolAddress((void**)&ptok, g_tok);
    cudaGetSymbolAddress((void**)&pwTh, g_wTh);

    __half* ipwT = pwTh;                                  // [512,768]
    __half* iwT0 = pwTh + 512*768;                        // 4 x [1024,512]
    __half* owT0 = pwTh + 512*768 + 4*1024*512;           // 4 x [512,512]

    const int GSMEM = 3 * 32768;   // 98304 B
    cudaFuncSetAttribute(gemm_fp16<0>, cudaFuncAttributeMaxDynamicSharedMemorySize, GSMEM);
    cudaFuncSetAttribute(gemm_fp16<1>, cudaFuncAttributeMaxDynamicSharedMemorySize, GSMEM);

    // prep: weight transposes (fp16), token conversion, all a_pow tables
    transpose_h<<<dim3(C_/32, D_/32), 256>>>(ipw, ipwT, C_, D_);
    for (int i = 0; i < 4; i++) {
        transpose_h<<<dim3(D_/32, 2*D_/32), 256>>>(iw + (size_t)i*D_*2*D_, iwT0 + (size_t)i*2*D_*D_, D_, 2*D_);
        transpose_h<<<dim3(D_/32, D_/32), 256>>>(ow + (size_t)i*D_*D_, owT0 + (size_t)i*D_*D_, D_, D_);
    }
    tok2half<<<(M_*C_)/1024, 256>>>(tokens, ptok);
    ap_all_kernel<<<4*L_, 512>>>(al);

    // in_proj: (16384x768)@(768x512)
    gemm_fp16<0><<<dim3(D_/128, M_/128), 256, GSMEM>>>(ptok, ipwT, ipb, nullptr, px, M_, D_, C_);

    for (int i = 0; i < 4; i++) {
        const float* api  = pap  + (size_t)i * L_ * D_;
        const float* iapi = piap + (size_t)i * L_ * D_;
        ln_kernel<true><<<M_/8, 256>>>(px, nw + i*D_, nb + i*D_, phh);
        gemm_fp16<0><<<dim3(2*D_/128, M_/128), 256, GSMEM>>>(
            phh, iwT0 + (size_t)i*2*D_*D_, ib + i*2*D_, nullptr, pxg, M_, 2*D_, D_);
        conv_silu_kernel<<<B_*H_, 256>>>(pxg, cw + (size_t)i*9*D_, cb + i*D_, pu);
        scanA<<<(2*B_*NCH*D_)/256, 256>>>(pu, bb + i*D_, iapi);
        scanB<<<(4*B_*D_)/256, 256>>>();
        scanC_row<<<(B_*NCH*D_)/256, 256>>>(pu, bb + i*D_, api, iapi);
        scanC_col<<<(B_*NCH*D_)/256, 256>>>(pu, pxg, bb + i*D_, cc + i*D_, dd + i*D_, phh, api, iapi);
        gemm_fp16<1><<<dim3(D_/128, M_/128), 256, GSMEM>>>(
            phh, owT0 + (size_t)i*D_*D_, ob + i*D_, px, px, M_, D_, D_);
    }

    ln_kernel<false><<<M_/8, 256>>>(px, onw, onb, pu);
    pool_kernel<<<B_, 512>>>(pu, out);
}

// round 17
// speedup vs baseline: 5.1471x; 1.1133x over previous
#include <cuda_runtime.h>
#include <cuda_fp16.h>
#include <math.h>
#include <stdint.h>

#define B_ 16
#define H_ 32
#define W_ 32
#define D_ 512
#define L_ 1024           // H_*W_
#define C_ 768
#define M_ (B_*L_)        // 16384 rows
#define NCH 32
#define CHL 32

// ---- static scratch (no allocations allowed) ----
__device__ float  g_x  [M_*D_];          // residual stream (fp32)
__device__ float  g_xin[M_*D_];          // GEMM1 x_in half (fp32, dense)
__device__ __half g_gate[M_*D_];         // GEMM1 gate half, pre-sigmoided fp16
__device__ float  g_u  [M_*D_];          // conv+silu output / final LN out
__device__ __half g_yrow[M_*D_];         // row-orientation scan sum (fp16)
__device__ float  g_ap [4*L_*D_];        // a_pow tables (all 4 blocks)
__device__ float  g_iap[4*L_*D_];        // 1/a_pow tables
__device__ float  g_cs [4*B_*NCH*D_];    // chunk partial sums [dir][b][chunk][d]
__device__ __half g_hh [M_*D_];          // fp16 GEMM A operand (LN out / gated h)
__device__ __half g_tok[M_*C_];          // fp16 tokens
__device__ __half g_wTh[512*768 + 4*(1024*512 + 512*512)];  // fp16 transposed weights

__device__ __forceinline__ void cpasync16(unsigned saddr, const void* g){
    asm volatile("cp.async.cg.shared.global [%0], [%1], 16;" :: "r"(saddr), "l"(g));
}
__device__ __forceinline__ uint32_t smem_u32(const void* p){
    uint32_t a; asm("{ .reg .u64 t; cvta.to.shared.u64 t, %1; cvt.u32.u64 %0, t; }" : "=r"(a) : "l"(p));
    return a;
}
#define SWZ(o) ((o) ^ (((o) >> 3) & 0x70))

// ---------------- fp16 tensor-core GEMM: 128x128 tile, K-chunk 64, 3-stage ----------------
// A [M,K] half row-major, BT [N,K] half row-major. Accum fp32.
// MODE 0: C = A@B + bias (fp32 out)
// MODE 1: C = R + A@B + bias (fp32 out)
// MODE 2: cols<512 -> C (fp32, stride 512); cols>=512 -> Gp = sigmoid fp16 (stride 512)
template<int MODE>
__global__ void __launch_bounds__(256, 2) gemm_fp16(
    const __half* __restrict__ A, const __half* __restrict__ BT,
    const float* __restrict__ bias, const float* __restrict__ R,
    float* __restrict__ C, __half* __restrict__ Gp, int M, int N, int K)
{
    extern __shared__ char smc[];
    uint32_t sb = smem_u32(smc);
    const uint32_t ASZ = 16384, STSZ = 32768;   // A 128x64 half = 16KB; stage = 32KB
    int t = threadIdx.x;
    int lane = t & 31, wid = t >> 5;
    int bm = blockIdx.y << 7, bn = blockIdx.x << 7;
    int warpM = wid >> 2, warpN = wid & 3;       // 2x4 warps, 64x32 tile each
    int tg = lane & 3, gid = lane >> 2;

    float acc[4][4][4];
#pragma unroll
    for (int i = 0; i < 4; i++)
#pragma unroll
        for (int j = 0; j < 4; j++)
#pragma unroll
            for (int k = 0; k < 4; k++) acc[i][j][k] = 0.f;

    const __half* Ab = A  + (size_t)bm * K;
    const __half* Bb = BT + (size_t)bn * K;

    auto issue = [&](int kb, int st) {
        uint32_t sa = sb + st * STSZ;
#pragma unroll
        for (int j = 0; j < 4; j++) {
            int idx = t + 256*j;
            int r = idx >> 3, cc = idx & 7;
            cpasync16(sa + SWZ(r*128 + cc*16), Ab + (size_t)r * K + kb*64 + cc*8);
        }
        uint32_t sbf = sa + ASZ;
#pragma unroll
        for (int j = 0; j < 4; j++) {
            int idx = t + 256*j;
            int r = idx >> 3, cc = idx & 7;
            cpasync16(sbf + SWZ(r*128 + cc*16), Bb + (size_t)r * K + kb*64 + cc*8);
        }
        asm volatile("cp.async.commit_group;");
    };

    // ldmatrix lane-address components (constant across ks)
    int arow = (lane & 15);                         // + m0
    int acb  = (lane >> 4) << 4;                    // + k0b
    int brow = (lane & 7) + ((lane >> 4) << 3);     // + n0
    int bcb  = ((lane >> 3) & 1) << 4;              // + k0b

    int nkb = K >> 6;
    issue(0, 0);
    issue(1, 1);
    for (int kb = 0; kb < nkb; kb++) {
        if (kb + 1 < nkb) asm volatile("cp.async.wait_group 1;");
        else              asm volatile("cp.async.wait_group 0;");
        __syncthreads();              // stage kb visible; all warps done with stage kb-1
        int nx = kb + 2;
        if (nx < nkb) issue(nx, nx % 3);   // slot (kb-1)%3 — retired last iteration
        int st = kb % 3;
        uint32_t sa  = sb + st * STSZ;
        uint32_t sbf = sa + ASZ;
#pragma unroll
        for (int ks = 0; ks < 4; ks++) {
            int k0b = ks << 5;                       // 16 halfs = 32 bytes
            uint32_t a[4][4], bq[2][4];
#pragma unroll
            for (int mt = 0; mt < 4; mt++) {
                int m0 = warpM*64 + mt*16;
                uint32_t ad = sa + SWZ((m0 + arow)*128 + k0b + acb);
                asm volatile("ldmatrix.sync.aligned.m8n8.x4.shared.b16 {%0,%1,%2,%3}, [%4];"
                    : "=r"(a[mt][0]), "=r"(a[mt][1]), "=r"(a[mt][2]), "=r"(a[mt][3]) : "r"(ad));
            }
#pragma unroll
            for (int np = 0; np < 2; np++) {
                int n0 = warpN*32 + np*16;
                uint32_t ad = sbf + SWZ((n0 + brow)*128 + k0b + bcb);
                asm volatile("ldmatrix.sync.aligned.m8n8.x4.shared.b16 {%0,%1,%2,%3}, [%4];"
                    : "=r"(bq[np][0]), "=r"(bq[np][1]), "=r"(bq[np][2]), "=r"(bq[np][3]) : "r"(ad));
            }
#pragma unroll
            for (int mt = 0; mt < 4; mt++)
#pragma unroll
                for (int np = 0; np < 2; np++)
#pragma unroll
                    for (int hh = 0; hh < 2; hh++) {
                        int nt = np*2 + hh;
                        asm volatile(
                            "mma.sync.aligned.m16n8k16.row.col.f32.f16.f16.f32 "
                            "{%0,%1,%2,%3}, {%4,%5,%6,%7}, {%8,%9}, {%0,%1,%2,%3};"
                            : "+f"(acc[mt][nt][0]), "+f"(acc[mt][nt][1]),
                              "+f"(acc[mt][nt][2]), "+f"(acc[mt][nt][3])
                            : "r"(a[mt][0]), "r"(a[mt][1]), "r"(a[mt][2]), "r"(a[mt][3]),
                              "r"(bq[np][2*hh]), "r"(bq[np][2*hh+1]));
                    }
        }
    }

    // epilogue
    bool isGate = (MODE == 2) && (bn >= 512);
#pragma unroll
    for (int mt = 0; mt < 4; mt++) {
        int r0 = bm + warpM*64 + mt*16 + gid;
#pragma unroll
        for (int nt = 0; nt < 4; nt++) {
            int col = bn + warpN*32 + nt*8 + 2*tg;
            float b0 = bias[col], b1 = bias[col+1];
            float o0 = acc[mt][nt][0] + b0;
            float o1 = acc[mt][nt][1] + b1;
            float o2 = acc[mt][nt][2] + b0;
            float o3 = acc[mt][nt][3] + b1;
            if (MODE == 1) {
                float2 ra = *(const float2*)(R + (size_t)r0 * N + col);
                float2 rb = *(const float2*)(R + (size_t)(r0+8) * N + col);
                o0 += ra.x; o1 += ra.y; o2 += rb.x; o3 += rb.y;
            }
            if (MODE == 2) {
                if (isGate) {
                    int gc = col - 512;
                    float s0 = 1.f / (1.f + expf(-o0));
                    float s1 = 1.f / (1.f + expf(-o1));
                    float s2 = 1.f / (1.f + expf(-o2));
                    float s3 = 1.f / (1.f + expf(-o3));
                    *(__half2*)(Gp + (size_t)r0 * 512 + gc)     = __floats2half2_rn(s0, s1);
                    *(__half2*)(Gp + (size_t)(r0+8) * 512 + gc) = __floats2half2_rn(s2, s3);
                } else {
                    *(float2*)(C + (size_t)r0 * 512 + col)     = make_float2(o0, o1);
                    *(float2*)(C + (size_t)(r0+8) * 512 + col) = make_float2(o2, o3);
                }
            } else {
                *(float2*)(C + (size_t)r0 * N + col)     = make_float2(o0, o1);
                *(float2*)(C + (size_t)(r0+8) * N + col) = make_float2(o2, o3);
            }
        }
    }
}

// ---------------- transpose weights [K,N] -> [N,K], fp16 ----------------
__global__ void __launch_bounds__(256) transpose_h(
    const float* __restrict__ src, __half* __restrict__ dst, int K, int N)
{
    __shared__ float tile[32][33];
    int kx = blockIdx.x * 32, ny = blockIdx.y * 32;
    int tx = threadIdx.x & 31, ty0 = threadIdx.x >> 5;   // 32x8
#pragma unroll
    for (int j = 0; j < 32; j += 8) {
        int ty = ty0 + j;
        tile[ty][tx] = src[(size_t)(kx + ty) * N + ny + tx];
    }
    __syncthreads();
#pragma unroll
    for (int j = 0; j < 32; j += 8) {
        int ty = ty0 + j;
        dst[(size_t)(ny + ty) * K + kx + tx] = __float2half_rn(tile[tx][ty]);
    }
}

// ---------------- tokens -> fp16 ----------------
__global__ void __launch_bounds__(256) tok2half(
    const float* __restrict__ src, __half* __restrict__ dst)
{
    int i = (blockIdx.x * 256 + threadIdx.x) * 4;
    float4 v = *(const float4*)(src + i);
    *(__half2*)(dst + i)     = __floats2half2_rn(v.x, v.y);
    *(__half2*)(dst + i + 2) = __floats2half2_rn(v.z, v.w);
}

// ---------------- LayerNorm: one warp per row of 512; HOUT: fp16 output ----------------
template<bool HOUT>
__global__ void __launch_bounds__(256) ln_kernel(
    const float* __restrict__ x, const float* __restrict__ w,
    const float* __restrict__ b, void* __restrict__ outv)
{
    int row  = blockIdx.x * 8 + (threadIdx.x >> 5);
    int lane = threadIdx.x & 31;
    const float* xr = x + (size_t)row * D_;
    float4 v[4];
    float s = 0.f, sq = 0.f;
#pragma unroll
    for (int i = 0; i < 4; i++) {
        v[i] = *(const float4*)(xr + i*128 + lane*4);
        s  += v[i].x + v[i].y + v[i].z + v[i].w;
        sq += v[i].x*v[i].x + v[i].y*v[i].y + v[i].z*v[i].z + v[i].w*v[i].w;
    }
#pragma unroll
    for (int o = 16; o; o >>= 1) {
        s  += __shfl_xor_sync(0xffffffffu, s,  o);
        sq += __shfl_xor_sync(0xffffffffu, sq, o);
    }
    float mu  = s * (1.0f / D_);
    float var = sq * (1.0f / D_) - mu * mu;
    float rs  = rsqrtf(var + 1e-5f);
#pragma unroll
    for (int i = 0; i < 4; i++) {
        int col = i*128 + lane*4;
        float4 wv = *(const float4*)(w + col);
        float4 bv = *(const float4*)(b + col);
        float4 o;
        o.x = (v[i].x - mu) * rs * wv.x + bv.x;
        o.y = (v[i].y - mu) * rs * wv.y + bv.y;
        o.z = (v[i].z - mu) * rs * wv.z + bv.z;
        o.w = (v[i].w - mu) * rs * wv.w + bv.w;
        if (HOUT) {
            __half* orow = (__half*)outv + (size_t)row * D_;
            *(__half2*)(orow + col)     = __floats2half2_rn(o.x, o.y);
            *(__half2*)(orow + col + 2) = __floats2half2_rn(o.z, o.w);
        } else {
            float* orow = (float*)outv + (size_t)row * D_;
            *(float4*)(orow + col) = o;
        }
    }
}

// ------- depthwise 3x3 conv + bias + SiLU + row-orientation chunk sums (fused scanA-row) -------
// block = (b,h); 256 threads, 2 channels each. Row chunk index c == h (CHL == W == 32).
__global__ void __launch_bounds__(256) conv_silu_scan_kernel(
    const float* __restrict__ xin, const float* __restrict__ cw,
    const float* __restrict__ cb, const float* __restrict__ bvec,
    const float* __restrict__ iap, float* __restrict__ u)
{
    int bh = blockIdx.x;              // b*32 + h
    int d = threadIdx.x * 2;          // 2 channels per thread
    int h = bh & 31, b = bh >> 5;
    float2 Wk[3][3];
#pragma unroll
    for (int r = 0; r < 3; r++)
#pragma unroll
        for (int c = 0; c < 3; c++) Wk[r][c] = *(const float2*)(cw + (r*3 + c)*D_ + d);
    float2 bias = *(const float2*)(cb + d);
    float2 bd = *(const float2*)(bvec + d);
    const float* base = xin + ((size_t)(b << 10)) * D_ + d;
    bool hm = h > 0, hp = h < 31;
    const float2 z2 = make_float2(0.f, 0.f);
    float2 xm0 = z2, xm1 = z2, xm2 = z2;
    float2 xc0 = hm ? *(const float2*)(base + (size_t)((h-1)*32)*D_) : z2;
    float2 xc1 =      *(const float2*)(base + (size_t)( h   *32)*D_);
    float2 xc2 = hp ? *(const float2*)(base + (size_t)((h+1)*32)*D_) : z2;
    float* uo = u + (size_t)((b << 10) + (h << 5)) * D_ + d;
    float sfx = 0.f, sfy = 0.f, sbx = 0.f, sby = 0.f;
#pragma unroll 4
    for (int w = 0; w < 32; w++) {
        float2 xp0 = z2, xp1 = z2, xp2 = z2;
        if (w < 31) {
            xp0 = hm ? *(const float2*)(base + (size_t)((h-1)*32 + w+1)*D_) : z2;
            xp1 =      *(const float2*)(base + (size_t)( h   *32 + w+1)*D_);
            xp2 = hp ? *(const float2*)(base + (size_t)((h+1)*32 + w+1)*D_) : z2;
        }
        float ax = bias.x, ay = bias.y;
        ax += xm0.x*Wk[0][0].x + xc0.x*Wk[0][1].x + xp0.x*Wk[0][2].x;
        ay += xm0.y*Wk[0][0].y + xc0.y*Wk[0][1].y + xp0.y*Wk[0][2].y;
        ax += xm1.x*Wk[1][0].x + xc1.x*Wk[1][1].x + xp1.x*Wk[1][2].x;
        ay += xm1.y*Wk[1][0].y + xc1.y*Wk[1][1].y + xp1.y*Wk[1][2].y;
        ax += xm2.x*Wk[2][0].x + xc2.x*Wk[2][1].x + xp2.x*Wk[2][2].x;
        ay += xm2.y*Wk[2][0].y + xc2.y*Wk[2][1].y + xp2.y*Wk[2][2].y;
        float2 o;
        o.x = ax / (1.f + expf(-ax));
        o.y = ay / (1.f + expf(-ay));
        *(float2*)(uo + (size_t)w * D_) = o;
        // fused row-orientation chunk sums: s = h*32 + w
        int s = (h << 5) + w;
        float2 iapf = *(const float2*)(iap + (size_t)s * D_ + d);
        float2 iapb = *(const float2*)(iap + (size_t)(L_-1-s) * D_ + d);
        float uvx = o.x * bd.x, uvy = o.y * bd.y;
        sfx += uvx * iapf.x;  sfy += uvy * iapf.y;
        sbx += uvx * iapb.x;  sby += uvy * iapb.y;
        xm0 = xc0; xm1 = xc1; xm2 = xc2;
        xc0 = xp0; xc1 = xp1; xc2 = xp2;
    }
    size_t dstr = (size_t)B_*NCH*D_;
    size_t cbase = ((size_t)b*NCH)*D_ + d;
    *(float2*)&g_cs[cbase + (size_t)h*D_] = make_float2(sfx, sfy);
    *(float2*)&g_cs[dstr + cbase + (size_t)(NCH-1-h)*D_] = make_float2(sbx, sby);
}

// ---------------- a_pow tables for ALL 4 blocks (clamped log-domain form) ----------------
__global__ void __launch_bounds__(512) ap_all_kernel(const float* __restrict__ alog)
{
    int d = threadIdx.x;
    int t = blockIdx.x & (L_ - 1);
    int blk = blockIdx.x >> 10;
    float a = 1.f / (1.f + expf(-alog[blk*D_ + d]));
    a = fminf(fmaxf(a, 1e-4f), 1.f - 1e-4f);
    float ap = fmaxf(expf((float)t * logf(a)), 1e-20f);
    size_t off = (size_t)blk * L_ * D_ + t*D_ + d;
    g_ap [off] = ap;
    g_iap[off] = 1.f / ap;
}

// ---------------- pass A (col orientation only): per-chunk fwd+bwd partial sums ----------------
__global__ void __launch_bounds__(256) scanA_col(
    const float* __restrict__ u, const float* __restrict__ bvec,
    const float* __restrict__ iap)
{
    int tid = blockIdx.x * 256 + threadIdx.x;   // 16*32*512 = 262144
    int d = tid & 511;
    int c = (tid >> 9) & 31;
    int b = tid >> 14;
    float bd = bvec[d];
    const float* ub = u + ((size_t)b << 10) * D_ + d;
    float sf = 0.f, sb = 0.f;
#pragma unroll
    for (int i = 0; i < CHL; i++) {
        int s = c*CHL + i;
        int pos = ((s & 31) << 5) + (s >> 5);
        float uv = ub[(size_t)pos * D_] * bd;
        sf += uv * iap[s*D_ + d];
        sb += uv * iap[(L_-1-s)*D_ + d];
    }
    size_t dstr = (size_t)B_*NCH*D_;
    size_t base = 2 * dstr + ((size_t)b*NCH)*D_ + d;
    g_cs[base + (size_t)c*D_] = sf;
    g_cs[base + dstr + (size_t)(NCH-1-c)*D_] = sb;
}

// ---------------- pass B: exclusive prefix over 32 chunk sums per direction ----------------
__global__ void __launch_bounds__(256) scanB()
{
    int tid = blockIdx.x * 256 + threadIdx.x;   // 4*16*512 = 32768
    int d = tid & 511;
    int b = (tid >> 9) & 15;
    int dir = tid >> 13;
    size_t base = (((size_t)dir * B_ + b) * NCH) * D_ + d;
    float s = 0.f;
#pragma unroll
    for (int c = 0; c < NCH; c++) {
        float v = g_cs[base + (size_t)c * D_];
        g_cs[base + (size_t)c * D_] = s;
        s += v;
    }
}

// ---------------- pass C row: fwd+bwd replay, fp16 store of summed terms ----------------
__global__ void __launch_bounds__(256) scanC_row(
    const float* __restrict__ u, const float* __restrict__ bvec,
    const float* __restrict__ ap, const float* __restrict__ iap)
{
    int tid = blockIdx.x * 256 + threadIdx.x;   // 16*32*512 = 262144
    int d = tid & 511;
    int c = (tid >> 9) & 31;
    int b = tid >> 14;
    float bd = bvec[d];
    size_t dstr = (size_t)B_*NCH*D_;
    size_t csb = ((size_t)b*NCH)*D_ + d;
    float off_f = g_cs[csb + (size_t)c*D_];
    float off_b = g_cs[dstr + csb + (size_t)(NCH-1-c)*D_];
    const float* ub = u + ((size_t)b << 10) * D_ + d;
    __half* yr = g_yrow + ((size_t)b << 10) * D_ + d;
    float termb[CHL];
    float sb = off_b;
#pragma unroll
    for (int i = CHL-1; i >= 0; i--) {
        int s = c*CHL + i;
        int tb = L_-1-s;
        sb += ub[(size_t)s * D_] * bd * iap[tb*D_ + d];
        termb[i] = ap[tb*D_ + d] * sb;
    }
    float sf = off_f;
#pragma unroll
    for (int i = 0; i < CHL; i++) {
        int s = c*CHL + i;
        sf += ub[(size_t)s * D_] * bd * iap[s*D_ + d];
        yr[(size_t)s * D_] = __float2half_rn(ap[s*D_ + d] * sf + termb[i]);
    }
}

// ---------------- pass C col + combine + gate: writes fp16 GEMM A operand ----------------
__global__ void __launch_bounds__(256) scanC_col(
    const float* __restrict__ u, const __half* __restrict__ gate,
    const float* __restrict__ bvec, const float* __restrict__ cvec,
    const float* __restrict__ dvec, __half* __restrict__ hout,
    const float* __restrict__ ap, const float* __restrict__ iap)
{
    int tid = blockIdx.x * 256 + threadIdx.x;   // 262144
    int d = tid & 511;
    int c = (tid >> 9) & 31;
    int b = tid >> 14;
    float bd = bvec[d];
    size_t dstr = (size_t)B_*NCH*D_;
    size_t csb = ((size_t)b*NCH)*D_ + d;
    float off_f = g_cs[2*dstr + csb + (size_t)c*D_];
    float off_b = g_cs[3*dstr + csb + (size_t)(NCH-1-c)*D_];
    const float* ub = u + ((size_t)b << 10) * D_ + d;
    const __half* yr = g_yrow + ((size_t)b << 10) * D_ + d;
    const __half* gb = gate + ((size_t)b << 10) * D_ + d;
    __half* ho = hout + ((size_t)b << 10) * D_ + d;
    float cd = cvec[d], ddv = dvec[d];
    float termb[CHL];
    float sb = off_b;
#pragma unroll
    for (int i = CHL-1; i >= 0; i--) {
        int s = c*CHL + i;
        int pos = ((s & 31) << 5) + (s >> 5);
        int tb = L_-1-s;
        sb += ub[(size_t)pos * D_] * bd * iap[tb*D_ + d];
        termb[i] = ap[tb*D_ + d] * sb;
    }
    float sf = off_f;
#pragma unroll
    for (int i = 0; i < CHL; i++) {
        int s = c*CHL + i;
        int pos = ((s & 31) << 5) + (s >> 5);
        float uraw = ub[(size_t)pos * D_];
        sf += uraw * bd * iap[s*D_ + d];
        float vcol = ap[s*D_ + d] * sf + termb[i];
        float ysum = __half2float(yr[(size_t)pos * D_]) + vcol;
        float res = 0.25f * cd * ysum + ddv * uraw;
        float gt = __half2float(gb[(size_t)pos * D_]);
        ho[(size_t)pos * D_] = __float2half_rn(res * gt);
    }
}

// ---------------- mean pool over the 1024 grid positions ----------------
__global__ void __launch_bounds__(512) pool_kernel(
    const float* __restrict__ h, float* __restrict__ out)
{
    int b = blockIdx.x, d = threadIdx.x;
    const float* p = h + (size_t)b * L_ * D_ + d;
    double acc = 0.0;
    for (int t = 0; t < L_; t++) acc += (double)p[(size_t)t * D_];
    out[b*D_ + d] = (float)(acc * (1.0 / 1024.0));
}

extern "C" void kernel_launch(void* const* d_in, const int* in_sizes, int n_in,
                              void* d_out, int out_size)
{
    const float* tokens = (const float*)d_in[0];
    const float* ipw = (const float*)d_in[1];
    const float* ipb = (const float*)d_in[2];
    const float* nw  = (const float*)d_in[3];
    const float* nb  = (const float*)d_in[4];
    const float* iw  = (const float*)d_in[5];
    const float* ib  = (const float*)d_in[6];
    const float* cw  = (const float*)d_in[7];
    const float* cb  = (const float*)d_in[8];
    const float* al  = (const float*)d_in[9];
    const float* bb  = (const float*)d_in[10];
    const float* cc  = (const float*)d_in[11];
    const float* dd  = (const float*)d_in[12];
    const float* ow  = (const float*)d_in[13];
    const float* ob  = (const float*)d_in[14];
    const float* onw = (const float*)d_in[15];
    const float* onb = (const float*)d_in[16];
    float* out = (float*)d_out;

    float *px, *pxin, *pu, *pap, *piap;
    __half *phh, *ptok, *pwTh, *pgate;
    cudaGetSymbolAddress((void**)&px,    g_x);
    cudaGetSymbolAddress((void**)&pxin,  g_xin);
    cudaGetSymbolAddress((void**)&pu,    g_u);
    cudaGetSymbolAddress((void**)&pap,   g_ap);
    cudaGetSymbolAddress((void**)&piap,  g_iap);
    cudaGetSymbolAddress((void**)&phh,   g_hh);
    cudaGetSymbolAddress((void**)&ptok,  g_tok);
    cudaGetSymbolAddress((void**)&pwTh,  g_wTh);
    cudaGetSymbolAddress((void**)&pgate, g_gate);

    __half* ipwT = pwTh;                                  // [512,768]
    __half* iwT0 = pwTh + 512*768;                        // 4 x [1024,512]
    __half* owT0 = pwTh + 512*768 + 4*1024*512;           // 4 x [512,512]

    const int GSMEM = 3 * 32768;   // 98304 B
    cudaFuncSetAttribute(gemm_fp16<0>, cudaFuncAttributeMaxDynamicSharedMemorySize, GSMEM);
    cudaFuncSetAttribute(gemm_fp16<1>, cudaFuncAttributeMaxDynamicSharedMemorySize, GSMEM);
    cudaFuncSetAttribute(gemm_fp16<2>, cudaFuncAttributeMaxDynamicSharedMemorySize, GSMEM);

    // prep: weight transposes (fp16), token conversion, all a_pow tables
    transpose_h<<<dim3(C_/32, D_/32), 256>>>(ipw, ipwT, C_, D_);
    for (int i = 0; i < 4; i++) {
        transpose_h<<<dim3(D_/32, 2*D_/32), 256>>>(iw + (size_t)i*D_*2*D_, iwT0 + (size_t)i*2*D_*D_, D_, 2*D_);
        transpose_h<<<dim3(D_/32, D_/32), 256>>>(ow + (size_t)i*D_*D_, owT0 + (size_t)i*D_*D_, D_, D_);
    }
    tok2half<<<(M_*C_)/1024, 256>>>(tokens, ptok);
    ap_all_kernel<<<4*L_, 512>>>(al);

    // in_proj: (16384x768)@(768x512)
    gemm_fp16<0><<<dim3(D_/128, M_/128), 256, GSMEM>>>(ptok, ipwT, ipb, nullptr, px, nullptr, M_, D_, C_);

    for (int i = 0; i < 4; i++) {
        const float* api  = pap  + (size_t)i * L_ * D_;
        const float* iapi = piap + (size_t)i * L_ * D_;
        ln_kernel<true><<<M_/8, 256>>>(px, nw + i*D_, nb + i*D_, phh);
        gemm_fp16<2><<<dim3(2*D_/128, M_/128), 256, GSMEM>>>(
            phh, iwT0 + (size_t)i*2*D_*D_, ib + i*2*D_, nullptr, pxin, pgate, M_, 2*D_, D_);
        conv_silu_scan_kernel<<<B_*H_, 256>>>(pxin, cw + (size_t)i*9*D_, cb + i*D_, bb + i*D_, iapi, pu);
        scanA_col<<<(B_*NCH*D_)/256, 256>>>(pu, bb + i*D_, iapi);
        scanB<<<(4*B_*D_)/256, 256>>>();
        scanC_row<<<(B_*NCH*D_)/256, 256>>>(pu, bb + i*D_, api, iapi);
        scanC_col<<<(B_*NCH*D_)/256, 256>>>(pu, pgate, bb + i*D_, cc + i*D_, dd + i*D_, phh, api, iapi);
        gemm_fp16<1><<<dim3(D_/128, M_/128), 256, GSMEM>>>(
            phh, owT0 + (size_t)i*D_*D_, ob + i*D_, px, px, nullptr, M_, D_, D_);
    }

    ln_kernel<false><<<M_/8, 256>>>(px, onw, onb, pu);
    pool_kernel<<<B_, 512>>>(pu, out);
}